// round 14
// baseline (speedup 1.0000x reference)
#include <cuda_runtime.h>
#include <cuda_fp16.h>
#include <math.h>
#include <cstdint>

// ---------------- problem constants ----------------
#define B     1024
#define CIN   3
#define HW    32
#define GC    16
#define E     4
#define C1    64
#define C2    128
#define NC    100
#define FCIN  8192      // 128*8*8

#define NPIX  324       // 18*18 haloed conv1 output grid
#define ROWP  72        // padded row length (halves); 144B stride

#define OUT_PROBS_OFF (B*NC)
#define OUT_AUX_OFF   (B*NC + B*E)

typedef unsigned long long ull;

// ---- f32x2 helpers ----
__device__ __forceinline__ ull ffma2(ull a, ull b, ull c) {
    ull d;
    asm("fma.rn.f32x2 %0, %1, %2, %3;" : "=l"(d) : "l"(a), "l"(b), "l"(c));
    return d;
}
__device__ __forceinline__ ull pk(float lo, float hi) {
    ull r;
    asm("mov.b64 %0, {%1, %2};" : "=l"(r) : "f"(lo), "f"(hi));
    return r;
}
__device__ __forceinline__ void upk(ull v, float& lo, float& hi) {
    asm("mov.b64 {%0, %1}, %2;" : "=f"(lo), "=f"(hi) : "l"(v));
}

__device__ __forceinline__ uint32_t smem_u32(const void* p) {
    uint32_t a;
    asm("{ .reg .u64 t; cvta.to.shared.u64 t, %1; cvt.u32.u64 %0, t; }"
        : "=r"(a) : "l"(p));
    return a;
}
__device__ __forceinline__ void ldsm_x4(uint32_t& r0, uint32_t& r1,
                                        uint32_t& r2, uint32_t& r3, uint32_t a) {
    asm volatile("ldmatrix.sync.aligned.m8n8.x4.shared.b16 {%0,%1,%2,%3}, [%4];"
                 : "=r"(r0), "=r"(r1), "=r"(r2), "=r"(r3) : "r"(a));
}
__device__ __forceinline__ void mma16816(float* d, const uint32_t* a,
                                         uint32_t b0, uint32_t b1) {
    asm volatile(
        "mma.sync.aligned.m16n8k16.row.col.f32.f16.f16.f32 "
        "{%0,%1,%2,%3}, {%4,%5,%6,%7}, {%8,%9}, {%0,%1,%2,%3};"
        : "+f"(d[0]), "+f"(d[1]), "+f"(d[2]), "+f"(d[3])
        : "r"(a[0]), "r"(a[1]), "r"(a[2]), "r"(a[3]), "r"(b0), "r"(b1));
}

// ---------------- device scratch ----------------
__device__ float    g_buf2[(size_t)B * C2 * 8 * 8];   // conv2+pool out
__device__ float    g_fwT[(size_t)E * FCIN * NC];     // FC weights, [e][k][col]
__device__ int      g_bidx[B];
__device__ float    g_bw[B];
__device__ int      g_list[E * B];
__device__ int      g_count[E];
// conv2 weights in HMMA fragment-major layout:
// [e][tap][wm(4)][mt(2)][ks(4)][hl(2)][lane(32)][q(4)] as u32 (half2 pairs)
#define W2F_PER_TAP 8192
__device__ uint32_t g_w2f[(size_t)E * 9 * W2F_PER_TAP];

// ---------------- merged prep: w2 fragments + tiled fw transpose ------------
#define NW2_BLOCKS ((E * 9 * W2F_PER_TAP) / 256)      // 1152
#define NFW_TILES  (E * 4 * (FCIN / 32))              // 4 ctiles x 256 ktiles x E = 4096

__global__ void prep_kernel(const float* __restrict__ c2w,
                            const float* __restrict__ fw) {
    int tid = threadIdx.x;
    if (blockIdx.x < NW2_BLOCKS) {
        if (blockIdx.x == 0 && tid < E) g_count[tid] = 0;
        int i = blockIdx.x * 256 + tid;
        int q    = i & 3;
        int lane = (i >> 2) & 31;
        int hl   = (i >> 7) & 1;
        int ks   = (i >> 8) & 3;
        int mt   = (i >> 10) & 1;
        int wm   = (i >> 11) & 3;
        int rest = i >> 13;            // e*9 + tap
        int tap  = rest % 9;
        int e    = rest / 9;

        int row = (lane >> 2) + (q & 1) * 8;
        int kk  = 2 * (lane & 3) + (q >> 1) * 8;
        int co  = wm * 32 + mt * 16 + row;
        int ci  = ks * 16 + kk;

        float v0 = c2w[(((size_t)(e * C2 + co)) * C1 + ci) * 9 + tap];
        float v1 = c2w[(((size_t)(e * C2 + co)) * C1 + ci + 1) * 9 + tap];
        __half h0, h1;
        if (hl == 0) {
            h0 = __float2half_rn(v0);
            h1 = __float2half_rn(v1);
        } else {
            __half t0 = __float2half_rn(v0);
            __half t1 = __float2half_rn(v1);
            h0 = __float2half_rn(v0 - __half2float(t0));
            h1 = __float2half_rn(v1 - __half2float(t1));
        }
        __half2 p = __halves2half2(h0, h1);
        g_w2f[i] = *(uint32_t*)&p;
    } else {
        // tiled transpose [e][c][k] -> [e][k][c], 32x32 tiles
        __shared__ float tile[32][33];
        int t  = blockIdx.x - NW2_BLOCKS;       // 0..4095
        int e  = t >> 10;                       // 1024 tiles per expert
        int r  = t & 1023;
        int ct = r >> 8;                        // 0..3
        int kt = r & 255;                       // 0..255
        int tx = tid & 31, ty = tid >> 5;       // 32 x 8

        const float* src = fw + (size_t)e * NC * FCIN;
        float* dst = g_fwT + (size_t)e * FCIN * NC;
#pragma unroll
        for (int j = 0; j < 4; j++) {
            int c = ct * 32 + ty + j * 8;
            if (c < NC)
                tile[ty + j * 8][tx] = src[(size_t)c * FCIN + kt * 32 + tx];
        }
        __syncthreads();
        int c = ct * 32 + tx;
        if (c < NC) {
#pragma unroll
            for (int j = 0; j < 4; j++) {
                int k = kt * 32 + ty + j * 8;
                dst[(size_t)k * NC + c] = tile[tx][ty + j * 8];
            }
        }
    }
}

// ---------------- gating conv (3->16) + relu + GAP + router (fused) --------
__global__ void __launch_bounds__(256) gate_router_kernel(
    const float* __restrict__ x, const float* __restrict__ gcw,
    const float* __restrict__ gcb, const float* __restrict__ gfw,
    const float* __restrict__ gfb, float* __restrict__ out_probs)
{
    __shared__ float xs[CIN * 34 * 34];
    __shared__ float wg[GC * 27];
    __shared__ float gb[GC];
    __shared__ float red[256];
    __shared__ float gp16[GC];

    int b   = blockIdx.x;
    int tid = threadIdx.x;

    for (int i = tid; i < CIN * 34 * 34; i += 256) xs[i] = 0.f;
    __syncthreads();
    const float* xb = x + (size_t)b * CIN * HW * HW;
    for (int i = tid; i < CIN * HW * HW; i += 256) {
        int ci = i >> 10, y = (i >> 5) & 31, xx = i & 31;
        xs[(ci * 34 + y + 1) * 34 + xx + 1] = xb[i];
    }
    for (int i = tid; i < GC * 27; i += 256) wg[i] = gcw[i];
    if (tid < GC) gb[tid] = gcb[tid];
    __syncthreads();

    int co = tid >> 4;
    int ln = tid & 15;
    float w[27];
#pragma unroll
    for (int k = 0; k < 27; k++) w[k] = wg[co * 27 + k];
    float bias = gb[co];

    float s = 0.f;
    for (int p = ln; p < HW * HW; p += 16) {
        int y = p >> 5, xx = p & 31;
        float v = bias;
#pragma unroll
        for (int ci = 0; ci < CIN; ci++)
#pragma unroll
            for (int dy = 0; dy < 3; dy++)
#pragma unroll
                for (int dx = 0; dx < 3; dx++)
                    v = fmaf(xs[(ci * 34 + y + dy) * 34 + xx + dx],
                             w[ci * 9 + dy * 3 + dx], v);
        s += fmaxf(v, 0.f);
    }
    red[tid] = s;
    __syncthreads();
    if (ln == 0) {
        float t = 0.f;
#pragma unroll
        for (int j = 0; j < 16; j++) t += red[co * 16 + j];
        gp16[co] = t * (1.f / (HW * HW));
    }
    __syncthreads();

    // router tail (thread 0)
    if (tid == 0) {
        float lg[E];
#pragma unroll
        for (int e = 0; e < E; e++) {
            float v = gfb[e];
#pragma unroll
            for (int k = 0; k < GC; k++) v = fmaf(gp16[k], gfw[e * GC + k], v);
            lg[e] = v;
        }
        float mx = lg[0];
#pragma unroll
        for (int e = 1; e < E; e++) mx = fmaxf(mx, lg[e]);
        float ex[E], se = 0.f;
#pragma unroll
        for (int e = 0; e < E; e++) { ex[e] = expf(lg[e] - mx); se += ex[e]; }
        float inv = 1.f / se;
        float bw = -1.f; int bi = 0;
#pragma unroll
        for (int e = 0; e < E; e++) {
            float p = ex[e] * inv;
            out_probs[b * E + e] = p;
            if (p > bw) { bw = p; bi = e; }
        }
        g_bidx[b] = bi;
        g_bw[b]   = bw;
        int pos = atomicAdd(&g_count[bi], 1);
        g_list[bi * B + pos] = b;
    }
}

// ---------------- aux loss ----------------
__global__ void aux_kernel(const float* __restrict__ probs, float* __restrict__ out)
{
    __shared__ float sm[256 * E];
    int tid = threadIdx.x;
    float s[E] = {0.f, 0.f, 0.f, 0.f};
    for (int i = tid; i < B; i += 256) {
#pragma unroll
        for (int e = 0; e < E; e++) s[e] += probs[i * E + e];
    }
#pragma unroll
    for (int e = 0; e < E; e++) sm[tid * E + e] = s[e];
    __syncthreads();
    for (int st = 128; st > 0; st >>= 1) {
        if (tid < st)
#pragma unroll
            for (int e = 0; e < E; e++) sm[tid * E + e] += sm[(tid + st) * E + e];
        __syncthreads();
    }
    if (tid == 0) {
        float a = 0.f;
#pragma unroll
        for (int e = 0; e < E; e++) {
            float m = sm[e] * (1.f / B) - 1.f / E;
            a += m * m;
        }
        out[0] = a * (1.f / E);
    }
}

// ---------------- fused conv1 + conv2 (A fragments direct from gmem) -------
#define OFF_BH2   0
#define OFF_BL2   (NPIX * ROWP * 2)                 // 46656
#define OFF_XS    (2 * NPIX * ROWP * 2)             // 93312
#define C2_SMEM   (OFF_XS + CIN * 34 * 34 * 4)      // 107184

__global__ void __launch_bounds__(512, 1) conv12_fused_kernel(
    const float* __restrict__ x, const float* __restrict__ c1w,
    const float* __restrict__ c1b, const float* __restrict__ c2b)
{
    extern __shared__ char smem[];
    __shared__ float ws[C1 * 27];
    __shared__ float bs[C1];
    uint32_t sb = smem_u32(smem);

    int b    = blockIdx.x;
    int tid  = threadIdx.x;
    int wid  = tid >> 5;
    int lane = tid & 31;
    int e    = g_bidx[b];

    float* xs = (float*)(smem + OFF_XS);

    {
        uint32_t* bz = (uint32_t*)(smem + OFF_BH2);
        for (int i = tid; i < NPIX * ROWP; i += 512) bz[i] = 0;  // BH+BL
        for (int i = tid; i < CIN * 34 * 34; i += 512) xs[i] = 0.f;
    }
    __syncthreads();
    {
        const float* xb = x + (size_t)b * CIN * HW * HW;
        for (int i = tid; i < CIN * HW * HW; i += 512) {
            int ci = i >> 10, y = (i >> 5) & 31, xx = i & 31;
            xs[(ci * 34 + y + 1) * 34 + xx + 1] = xb[i];
        }
        const float* wsrc = c1w + (size_t)e * C1 * 27;
        for (int i = tid; i < C1 * 27; i += 512) ws[i] = wsrc[i];
        if (tid < C1) bs[tid] = c1b[e * C1 + tid];
    }
    __syncthreads();

    // ---- conv1: FFMA2 over x-pairs; write pooled hi/lo into B arrays ----
    {
        int co  = tid >> 3;      // 0..63
        int oct = tid & 7;
        float wr[27];
#pragma unroll
        for (int k = 0; k < 27; k++) wr[k] = ws[co * 27 + k];
        float bias = bs[co];
        ull bias2 = pk(bias, bias);
        __half* BHp = (__half*)(smem + OFF_BH2);
        __half* BLp = (__half*)(smem + OFF_BL2);

        for (int pr = 0; pr < 2; pr++) {
            int py = oct * 2 + pr;
            int Y  = 2 * py;
            for (int pg = 0; pg < 2; pg++) {
                ull acc0[8], acc1[8];
#pragma unroll
                for (int j = 0; j < 8; j++) { acc0[j] = bias2; acc1[j] = bias2; }
#pragma unroll
                for (int ci = 0; ci < CIN; ci++) {
                    ull w2[9];
#pragma unroll
                    for (int k = 0; k < 9; k++) w2[k] = pk(wr[ci * 9 + k], wr[ci * 9 + k]);
#pragma unroll
                    for (int j = 0; j < 8; j++) {
                        int X = 2 * (pg * 8 + j);
                        const float* base = &xs[(ci * 34 + Y) * 34 + X];
                        ull q[4][3];
#pragma unroll
                        for (int r = 0; r < 4; r++) {
                            float2 ra = *(const float2*)(base + r * 34);
                            float2 rb = *(const float2*)(base + r * 34 + 2);
                            q[r][0] = pk(ra.x, ra.y);
                            q[r][1] = pk(ra.y, rb.x);
                            q[r][2] = pk(rb.x, rb.y);
                        }
#pragma unroll
                        for (int dy = 0; dy < 3; dy++)
#pragma unroll
                            for (int dxj = 0; dxj < 3; dxj++) {
                                acc0[j] = ffma2(q[dy][dxj],     w2[dy * 3 + dxj], acc0[j]);
                                acc1[j] = ffma2(q[dy + 1][dxj], w2[dy * 3 + dxj], acc1[j]);
                            }
                    }
                }
#pragma unroll
                for (int j = 0; j < 8; j++) {
                    int px = pg * 8 + j;
                    float a00, a01, a10, a11;
                    upk(acc0[j], a00, a01);
                    upk(acc1[j], a10, a11);
                    float v = fmaxf(fmaxf(fmaxf(a00, a01), fmaxf(a10, a11)), 0.f);
                    __half h = __float2half_rn(v);
                    int pix = (py + 1) * 18 + (px + 1);
                    BHp[pix * ROWP + co] = h;
                    BLp[pix * ROWP + co] = __float2half_rn(v - __half2float(h));
                }
            }
        }
    }
    __syncthreads();

    // ---- conv2: tap GEMMs, A fragments straight from gmem ----
    int warp_m  = wid >> 2;
    int warp_n  = wid & 3;
    int co_base = warp_m * 32;

    float acc[2][8][4];
#pragma unroll
    for (int mt = 0; mt < 2; mt++)
#pragma unroll
        for (int nt = 0; nt < 8; nt++)
#pragma unroll
            for (int j = 0; j < 4; j++) acc[mt][nt][j] = 0.f;

    uint32_t b_off = (uint32_t)(((lane & 7) + ((lane >> 4) << 3)) * ROWP * 2)
                   + (uint32_t)(((lane >> 3) & 1) * 16);

    const uint4* afrag_e = (const uint4*)g_w2f
                         + (size_t)e * 9 * (W2F_PER_TAP / 4)
                         + (size_t)warp_m * 512 + lane;

    for (int tap = 0; tap < 9; tap++) {
        int dy = tap / 3, dx = tap % 3;
        const uint4* abase = afrag_e + (size_t)tap * (W2F_PER_TAP / 4);

#pragma unroll
        for (int ks = 0; ks < 4; ks++) {
            uint32_t kso = (uint32_t)(ks * 32);
            uint32_t a_h[2][4], a_l[2][4];
#pragma unroll
            for (int mt = 0; mt < 2; mt++) {
                uint4 vh = abase[((mt * 4 + ks) * 2 + 0) * 32];
                uint4 vl = abase[((mt * 4 + ks) * 2 + 1) * 32];
                a_h[mt][0] = vh.x; a_h[mt][1] = vh.y;
                a_h[mt][2] = vh.z; a_h[mt][3] = vh.w;
                a_l[mt][0] = vl.x; a_l[mt][1] = vl.y;
                a_l[mt][2] = vl.z; a_l[mt][3] = vl.w;
            }
#pragma unroll
            for (int ntp = 0; ntp < 4; ntp++) {
                int y  = warp_n * 4 + ntp;
                uint32_t rrow = (uint32_t)((y + dy) * 18 + dx);
                uint32_t rb   = rrow * (ROWP * 2) + b_off + kso;
                uint32_t bh0, bh1, bh2, bh3, bl0, bl1, bl2, bl3;
                ldsm_x4(bh0, bh1, bh2, bh3, sb + OFF_BH2 + rb);
                ldsm_x4(bl0, bl1, bl2, bl3, sb + OFF_BL2 + rb);
                int nt0 = 2 * ntp, nt1 = 2 * ntp + 1;
                mma16816(acc[0][nt0], a_h[0], bh0, bh1);
                mma16816(acc[1][nt0], a_h[1], bh0, bh1);
                mma16816(acc[0][nt1], a_h[0], bh2, bh3);
                mma16816(acc[1][nt1], a_h[1], bh2, bh3);
                mma16816(acc[0][nt0], a_h[0], bl0, bl1);
                mma16816(acc[1][nt0], a_h[1], bl0, bl1);
                mma16816(acc[0][nt1], a_h[0], bl2, bl3);
                mma16816(acc[1][nt1], a_h[1], bl2, bl3);
                mma16816(acc[0][nt0], a_l[0], bh0, bh1);
                mma16816(acc[1][nt0], a_l[1], bh0, bh1);
                mma16816(acc[0][nt1], a_l[0], bh2, bh3);
                mma16816(acc[1][nt1], a_l[1], bh2, bh3);
            }
        }
    }

    int r  = lane >> 2;
    int c2 = lane & 3;
    float* dstb = g_buf2 + (size_t)b * FCIN;
#pragma unroll
    for (int mt = 0; mt < 2; mt++) {
#pragma unroll
        for (int rg = 0; rg < 2; rg++) {
            int co = co_base + mt * 16 + r + rg * 8;
            float bias = c2b[e * C2 + co];
#pragma unroll
            for (int q = 0; q < 4; q++) {
                int ntp = (q & 1) + (q >> 1) * 4;   // 0,1,4,5
                float m = fmaxf(
                    fmaxf(acc[mt][ntp][rg * 2],     acc[mt][ntp][rg * 2 + 1]),
                    fmaxf(acc[mt][ntp + 2][rg * 2], acc[mt][ntp + 2][rg * 2 + 1]));
                int py = warp_n * 2 + (ntp >> 2);
                int px = (ntp & 1) * 4 + c2;
                dstb[co * 64 + py * 8 + px] = fmaxf(m + bias, 0.f);
            }
        }
    }
}

// ---------------- expert FC: blocked GEMM, 32 samples x 50 cols per block ---
#define FC_SPB    32
#define FC_KCHUNK 128
#define FC_COLH   50
#define FC_WS_FLOATS (FC_KCHUNK * FC_COLH)             // 6400
#define FC_AS_FLOATS (FC_KCHUNK * FC_SPB)              // 4096
#define FC_SMEM ((FC_WS_FLOATS + FC_AS_FLOATS) * 4)    // 41984 bytes

__global__ void __launch_bounds__(256) fc_kernel(
    const float* __restrict__ fb, float* __restrict__ out)
{
    extern __shared__ float fsm[];
    float* Wsm = fsm;                       // [128][50]
    float* Asm = fsm + FC_WS_FLOATS;        // [128][32]
    __shared__ int sidx[FC_SPB];

    int bi    = blockIdx.x;
    int e     = bi >> 6;                    // 64 blocks per expert
    int rest  = bi & 63;
    int chunk = rest >> 1;                  // 0..31
    int ch    = rest & 1;                   // column half
    int n  = g_count[e];
    int s0 = chunk * FC_SPB;
    if (s0 >= n) return;
    int m = n - s0; if (m > FC_SPB) m = FC_SPB;

    int tid = threadIdx.x;
    if (tid < FC_SPB) {
        int idx = s0 + tid; if (idx >= n) idx = n - 1;
        sidx[tid] = g_list[e * B + idx];
    }
    __syncthreads();

    int cg = tid % 25;                 // col pair 0..24
    int sg = tid / 25;                 // 0..9; active if <8 (4 samples each)
    bool act = (sg < 8);

    ull c0[2], c1[2];
#pragma unroll
    for (int p = 0; p < 2; p++) { c0[p] = 0; c1[p] = 0; }

    const float* wsrc_e = g_fwT + (size_t)e * FCIN * NC + ch * FC_COLH;

    for (int k0 = 0; k0 < FCIN; k0 += FC_KCHUNK) {
        __syncthreads();
        for (int i = tid; i < FC_KCHUNK * 25; i += 256) {
            int kk = i / 25, c2i = i % 25;
            *(float2*)&Wsm[kk * FC_COLH + c2i * 2] =
                *(const float2*)&wsrc_e[(size_t)(k0 + kk) * NC + c2i * 2];
        }
        for (int i = tid; i < FC_SPB * (FC_KCHUNK / 4); i += 256) {
            int s   = i >> 5;
            int seg = i & 31;
            float4 v = *(const float4*)&g_buf2[(size_t)sidx[s] * FCIN + k0 + seg * 4];
            Asm[(seg * 4 + 0) * FC_SPB + s] = v.x;
            Asm[(seg * 4 + 1) * FC_SPB + s] = v.y;
            Asm[(seg * 4 + 2) * FC_SPB + s] = v.z;
            Asm[(seg * 4 + 3) * FC_SPB + s] = v.w;
        }
        __syncthreads();
        if (act) {
            const float* wp = Wsm + cg * 2;
            const float* ap = Asm + sg * 4;
#pragma unroll 4
            for (int kk = 0; kk < FC_KCHUNK; kk++) {
                float2 w = *(const float2*)(wp + kk * FC_COLH);
                ull ww0 = pk(w.x, w.x);
                ull ww1 = pk(w.y, w.y);
                const ull* arow = (const ull*)(ap + kk * FC_SPB);
#pragma unroll
                for (int p = 0; p < 2; p++) {
                    ull aa = arow[p];
                    c0[p] = ffma2(aa, ww0, c0[p]);
                    c1[p] = ffma2(aa, ww1, c1[p]);
                }
            }
        }
    }

    if (act) {
        int colb = ch * FC_COLH + cg * 2;
        float b0 = fb[e * NC + colb];
        float b1 = fb[e * NC + colb + 1];
#pragma unroll
        for (int p = 0; p < 2; p++) {
            float v0lo, v0hi, v1lo, v1hi;
            upk(c0[p], v0lo, v0hi);
            upk(c1[p], v1lo, v1hi);
            int r0 = sg * 4 + 2 * p;
            if (r0 < m) {
                int s = sidx[r0];
                float sc = g_bw[s];
                out[(size_t)s * NC + colb]     = (v0lo + b0) * sc;
                out[(size_t)s * NC + colb + 1] = (v1lo + b1) * sc;
            }
            if (r0 + 1 < m) {
                int s = sidx[r0 + 1];
                float sc = g_bw[s];
                out[(size_t)s * NC + colb]     = (v0hi + b0) * sc;
                out[(size_t)s * NC + colb + 1] = (v1hi + b1) * sc;
            }
        }
    }
}

// ---------------- launch ----------------
extern "C" void kernel_launch(void* const* d_in, const int* in_sizes, int n_in,
                              void* d_out, int out_size)
{
    const float* x       = (const float*)d_in[0];
    const float* gate_cw = (const float*)d_in[1];
    const float* gate_cb = (const float*)d_in[2];
    const float* gate_fw = (const float*)d_in[3];
    const float* gate_fb = (const float*)d_in[4];
    const float* e_c1w   = (const float*)d_in[5];
    const float* e_c1b   = (const float*)d_in[6];
    const float* e_c2w   = (const float*)d_in[7];
    const float* e_c2b   = (const float*)d_in[8];
    const float* e_fw    = (const float*)d_in[9];
    const float* e_fb    = (const float*)d_in[10];
    float* out = (float*)d_out;

    cudaFuncSetAttribute(conv12_fused_kernel,
                         cudaFuncAttributeMaxDynamicSharedMemorySize, C2_SMEM);
    cudaFuncSetAttribute(fc_kernel,
                         cudaFuncAttributeMaxDynamicSharedMemorySize, FC_SMEM);

    prep_kernel<<<NW2_BLOCKS + NFW_TILES, 256>>>(e_c2w, e_fw);               // 0
    gate_router_kernel<<<B, 256>>>(x, gate_cw, gate_cb, gate_fw, gate_fb,
                                   out + OUT_PROBS_OFF);                     // 1
    aux_kernel<<<1, 256>>>(out + OUT_PROBS_OFF, out + OUT_AUX_OFF);          // 2
    conv12_fused_kernel<<<B, 512, C2_SMEM>>>(x, e_c1w, e_c1b, e_c2b);        // 3 (ncu)
    fc_kernel<<<E * 64, 256, FC_SMEM>>>(e_fb, out);                          // 4
}

// round 15
// speedup vs baseline: 1.2398x; 1.2398x over previous
#include <cuda_runtime.h>
#include <cuda_fp16.h>
#include <math.h>
#include <cstdint>

// ---------------- problem constants ----------------
#define B     1024
#define CIN   3
#define HW    32
#define GC    16
#define E     4
#define C1    64
#define C2    128
#define NC    100
#define FCIN  8192      // 128*8*8

#define NPIX  324       // 18*18 haloed conv1 output grid
#define ROWP  72        // padded row length (halves); 144B stride

#define OUT_PROBS_OFF (B*NC)
#define OUT_AUX_OFF   (B*NC + B*E)

typedef unsigned long long ull;

// ---- f32x2 helpers ----
__device__ __forceinline__ ull ffma2(ull a, ull b, ull c) {
    ull d;
    asm("fma.rn.f32x2 %0, %1, %2, %3;" : "=l"(d) : "l"(a), "l"(b), "l"(c));
    return d;
}
__device__ __forceinline__ ull pk(float lo, float hi) {
    ull r;
    asm("mov.b64 %0, {%1, %2};" : "=l"(r) : "f"(lo), "f"(hi));
    return r;
}
__device__ __forceinline__ void upk(ull v, float& lo, float& hi) {
    asm("mov.b64 {%0, %1}, %2;" : "=f"(lo), "=f"(hi) : "l"(v));
}

__device__ __forceinline__ uint32_t smem_u32(const void* p) {
    uint32_t a;
    asm("{ .reg .u64 t; cvta.to.shared.u64 t, %1; cvt.u32.u64 %0, t; }"
        : "=r"(a) : "l"(p));
    return a;
}
__device__ __forceinline__ void ldsm_x4(uint32_t& r0, uint32_t& r1,
                                        uint32_t& r2, uint32_t& r3, uint32_t a) {
    asm volatile("ldmatrix.sync.aligned.m8n8.x4.shared.b16 {%0,%1,%2,%3}, [%4];"
                 : "=r"(r0), "=r"(r1), "=r"(r2), "=r"(r3) : "r"(a));
}
__device__ __forceinline__ void mma16816(float* d, const uint32_t* a,
                                         uint32_t b0, uint32_t b1) {
    asm volatile(
        "mma.sync.aligned.m16n8k16.row.col.f32.f16.f16.f32 "
        "{%0,%1,%2,%3}, {%4,%5,%6,%7}, {%8,%9}, {%0,%1,%2,%3};"
        : "+f"(d[0]), "+f"(d[1]), "+f"(d[2]), "+f"(d[3])
        : "r"(a[0]), "r"(a[1]), "r"(a[2]), "r"(a[3]), "r"(b0), "r"(b1));
}

// ---------------- device scratch ----------------
__device__ float    g_buf2[(size_t)B * C2 * 8 * 8];   // conv2+pool out
__device__ float    g_fwT[(size_t)E * FCIN * NC];     // FC weights, [e][k][col]
__device__ float    g_fcp[4 * (size_t)B * NC];        // FC k-split partials
__device__ int      g_bidx[B];
__device__ float    g_bw[B];
__device__ int      g_list[E * B];
__device__ int      g_count[E];
// conv2 weights in HMMA fragment-major layout:
// [e][tap][wm(4)][mt(2)][ks(4)][hl(2)][lane(32)][q(4)] as u32 (half2 pairs)
#define W2F_PER_TAP 8192
__device__ uint32_t g_w2f[(size_t)E * 9 * W2F_PER_TAP];

// ---------------- merged prep: w2 fragments + tiled fw transpose ------------
#define NW2_BLOCKS ((E * 9 * W2F_PER_TAP) / 256)      // 1152
#define NFW_TILES  (E * 4 * (FCIN / 32))              // 4096

__global__ void prep_kernel(const float* __restrict__ c2w,
                            const float* __restrict__ fw) {
    int tid = threadIdx.x;
    if (blockIdx.x < NW2_BLOCKS) {
        if (blockIdx.x == 0 && tid < E) g_count[tid] = 0;
        int i = blockIdx.x * 256 + tid;
        int q    = i & 3;
        int lane = (i >> 2) & 31;
        int hl   = (i >> 7) & 1;
        int ks   = (i >> 8) & 3;
        int mt   = (i >> 10) & 1;
        int wm   = (i >> 11) & 3;
        int rest = i >> 13;            // e*9 + tap
        int tap  = rest % 9;
        int e    = rest / 9;

        int row = (lane >> 2) + (q & 1) * 8;
        int kk  = 2 * (lane & 3) + (q >> 1) * 8;
        int co  = wm * 32 + mt * 16 + row;
        int ci  = ks * 16 + kk;

        float v0 = c2w[(((size_t)(e * C2 + co)) * C1 + ci) * 9 + tap];
        float v1 = c2w[(((size_t)(e * C2 + co)) * C1 + ci + 1) * 9 + tap];
        __half h0, h1;
        if (hl == 0) {
            h0 = __float2half_rn(v0);
            h1 = __float2half_rn(v1);
        } else {
            __half t0 = __float2half_rn(v0);
            __half t1 = __float2half_rn(v1);
            h0 = __float2half_rn(v0 - __half2float(t0));
            h1 = __float2half_rn(v1 - __half2float(t1));
        }
        __half2 p = __halves2half2(h0, h1);
        g_w2f[i] = *(uint32_t*)&p;
    } else {
        __shared__ float tile[32][33];
        int t  = blockIdx.x - NW2_BLOCKS;
        int e  = t >> 10;
        int r  = t & 1023;
        int ct = r >> 8;
        int kt = r & 255;
        int tx = tid & 31, ty = tid >> 5;

        const float* src = fw + (size_t)e * NC * FCIN;
        float* dst = g_fwT + (size_t)e * FCIN * NC;
#pragma unroll
        for (int j = 0; j < 4; j++) {
            int c = ct * 32 + ty + j * 8;
            if (c < NC)
                tile[ty + j * 8][tx] = src[(size_t)c * FCIN + kt * 32 + tx];
        }
        __syncthreads();
        int c = ct * 32 + tx;
        if (c < NC) {
#pragma unroll
            for (int j = 0; j < 4; j++) {
                int k = kt * 32 + ty + j * 8;
                dst[(size_t)k * NC + c] = tile[tx][ty + j * 8];
            }
        }
    }
}

// ---------------- gating conv (3->16) + relu + GAP + router (fused) --------
__global__ void __launch_bounds__(256) gate_router_kernel(
    const float* __restrict__ x, const float* __restrict__ gcw,
    const float* __restrict__ gcb, const float* __restrict__ gfw,
    const float* __restrict__ gfb, float* __restrict__ out_probs)
{
    __shared__ float xs[CIN * 34 * 34];
    __shared__ float wg[GC * 27];
    __shared__ float gb[GC];
    __shared__ float red[256];
    __shared__ float gp16[GC];

    int b   = blockIdx.x;
    int tid = threadIdx.x;

    for (int i = tid; i < CIN * 34 * 34; i += 256) xs[i] = 0.f;
    __syncthreads();
    const float* xb = x + (size_t)b * CIN * HW * HW;
    for (int i = tid; i < CIN * HW * HW; i += 256) {
        int ci = i >> 10, y = (i >> 5) & 31, xx = i & 31;
        xs[(ci * 34 + y + 1) * 34 + xx + 1] = xb[i];
    }
    for (int i = tid; i < GC * 27; i += 256) wg[i] = gcw[i];
    if (tid < GC) gb[tid] = gcb[tid];
    __syncthreads();

    int co = tid >> 4;
    int ln = tid & 15;
    float w[27];
#pragma unroll
    for (int k = 0; k < 27; k++) w[k] = wg[co * 27 + k];
    float bias = gb[co];

    float s = 0.f;
    for (int p = ln; p < HW * HW; p += 16) {
        int y = p >> 5, xx = p & 31;
        float v = bias;
#pragma unroll
        for (int ci = 0; ci < CIN; ci++)
#pragma unroll
            for (int dy = 0; dy < 3; dy++)
#pragma unroll
                for (int dx = 0; dx < 3; dx++)
                    v = fmaf(xs[(ci * 34 + y + dy) * 34 + xx + dx],
                             w[ci * 9 + dy * 3 + dx], v);
        s += fmaxf(v, 0.f);
    }
    red[tid] = s;
    __syncthreads();
    if (ln == 0) {
        float t = 0.f;
#pragma unroll
        for (int j = 0; j < 16; j++) t += red[co * 16 + j];
        gp16[co] = t * (1.f / (HW * HW));
    }
    __syncthreads();

    if (tid == 0) {
        float lg[E];
#pragma unroll
        for (int e = 0; e < E; e++) {
            float v = gfb[e];
#pragma unroll
            for (int k = 0; k < GC; k++) v = fmaf(gp16[k], gfw[e * GC + k], v);
            lg[e] = v;
        }
        float mx = lg[0];
#pragma unroll
        for (int e = 1; e < E; e++) mx = fmaxf(mx, lg[e]);
        float ex[E], se = 0.f;
#pragma unroll
        for (int e = 0; e < E; e++) { ex[e] = expf(lg[e] - mx); se += ex[e]; }
        float inv = 1.f / se;
        float bw = -1.f; int bi = 0;
#pragma unroll
        for (int e = 0; e < E; e++) {
            float p = ex[e] * inv;
            out_probs[b * E + e] = p;
            if (p > bw) { bw = p; bi = e; }
        }
        g_bidx[b] = bi;
        g_bw[b]   = bw;
        int pos = atomicAdd(&g_count[bi], 1);
        g_list[bi * B + pos] = b;
    }
}

// ---------------- aux loss ----------------
__global__ void aux_kernel(const float* __restrict__ probs, float* __restrict__ out)
{
    __shared__ float sm[256 * E];
    int tid = threadIdx.x;
    float s[E] = {0.f, 0.f, 0.f, 0.f};
    for (int i = tid; i < B; i += 256) {
#pragma unroll
        for (int e = 0; e < E; e++) s[e] += probs[i * E + e];
    }
#pragma unroll
    for (int e = 0; e < E; e++) sm[tid * E + e] = s[e];
    __syncthreads();
    for (int st = 128; st > 0; st >>= 1) {
        if (tid < st)
#pragma unroll
            for (int e = 0; e < E; e++) sm[tid * E + e] += sm[(tid + st) * E + e];
        __syncthreads();
    }
    if (tid == 0) {
        float a = 0.f;
#pragma unroll
        for (int e = 0; e < E; e++) {
            float m = sm[e] * (1.f / B) - 1.f / E;
            a += m * m;
        }
        out[0] = a * (1.f / E);
    }
}

// ---------------- fused conv1 + conv2 (A fragments direct from gmem) -------
#define OFF_BH2   0
#define OFF_BL2   (NPIX * ROWP * 2)                 // 46656
#define OFF_XS    (2 * NPIX * ROWP * 2)             // 93312
#define C2_SMEM   (OFF_XS + CIN * 34 * 34 * 4)      // 107184

__global__ void __launch_bounds__(512, 1) conv12_fused_kernel(
    const float* __restrict__ x, const float* __restrict__ c1w,
    const float* __restrict__ c1b, const float* __restrict__ c2b)
{
    extern __shared__ char smem[];
    __shared__ float ws[C1 * 27];
    __shared__ float bs[C1];
    uint32_t sb = smem_u32(smem);

    int b    = blockIdx.x;
    int tid  = threadIdx.x;
    int wid  = tid >> 5;
    int lane = tid & 31;
    int e    = g_bidx[b];

    float* xs = (float*)(smem + OFF_XS);

    {
        uint32_t* bz = (uint32_t*)(smem + OFF_BH2);
        for (int i = tid; i < NPIX * ROWP; i += 512) bz[i] = 0;  // BH+BL
        for (int i = tid; i < CIN * 34 * 34; i += 512) xs[i] = 0.f;
    }
    __syncthreads();
    {
        const float* xb = x + (size_t)b * CIN * HW * HW;
        for (int i = tid; i < CIN * HW * HW; i += 512) {
            int ci = i >> 10, y = (i >> 5) & 31, xx = i & 31;
            xs[(ci * 34 + y + 1) * 34 + xx + 1] = xb[i];
        }
        const float* wsrc = c1w + (size_t)e * C1 * 27;
        for (int i = tid; i < C1 * 27; i += 512) ws[i] = wsrc[i];
        if (tid < C1) bs[tid] = c1b[e * C1 + tid];
    }
    __syncthreads();

    // ---- conv1: FFMA2 over x-pairs; write pooled hi/lo into B arrays ----
    {
        int co  = tid >> 3;
        int oct = tid & 7;
        float wr[27];
#pragma unroll
        for (int k = 0; k < 27; k++) wr[k] = ws[co * 27 + k];
        float bias = bs[co];
        ull bias2 = pk(bias, bias);
        __half* BHp = (__half*)(smem + OFF_BH2);
        __half* BLp = (__half*)(smem + OFF_BL2);

        for (int pr = 0; pr < 2; pr++) {
            int py = oct * 2 + pr;
            int Y  = 2 * py;
            for (int pg = 0; pg < 2; pg++) {
                ull acc0[8], acc1[8];
#pragma unroll
                for (int j = 0; j < 8; j++) { acc0[j] = bias2; acc1[j] = bias2; }
#pragma unroll
                for (int ci = 0; ci < CIN; ci++) {
                    ull w2[9];
#pragma unroll
                    for (int k = 0; k < 9; k++) w2[k] = pk(wr[ci * 9 + k], wr[ci * 9 + k]);
#pragma unroll
                    for (int j = 0; j < 8; j++) {
                        int X = 2 * (pg * 8 + j);
                        const float* base = &xs[(ci * 34 + Y) * 34 + X];
                        ull q[4][3];
#pragma unroll
                        for (int r = 0; r < 4; r++) {
                            float2 ra = *(const float2*)(base + r * 34);
                            float2 rb = *(const float2*)(base + r * 34 + 2);
                            q[r][0] = pk(ra.x, ra.y);
                            q[r][1] = pk(ra.y, rb.x);
                            q[r][2] = pk(rb.x, rb.y);
                        }
#pragma unroll
                        for (int dy = 0; dy < 3; dy++)
#pragma unroll
                            for (int dxj = 0; dxj < 3; dxj++) {
                                acc0[j] = ffma2(q[dy][dxj],     w2[dy * 3 + dxj], acc0[j]);
                                acc1[j] = ffma2(q[dy + 1][dxj], w2[dy * 3 + dxj], acc1[j]);
                            }
                    }
                }
#pragma unroll
                for (int j = 0; j < 8; j++) {
                    int px = pg * 8 + j;
                    float a00, a01, a10, a11;
                    upk(acc0[j], a00, a01);
                    upk(acc1[j], a10, a11);
                    float v = fmaxf(fmaxf(fmaxf(a00, a01), fmaxf(a10, a11)), 0.f);
                    __half h = __float2half_rn(v);
                    int pix = (py + 1) * 18 + (px + 1);
                    BHp[pix * ROWP + co] = h;
                    BLp[pix * ROWP + co] = __float2half_rn(v - __half2float(h));
                }
            }
        }
    }
    __syncthreads();

    // ---- conv2: tap GEMMs, A fragments straight from gmem ----
    int warp_m  = wid >> 2;
    int warp_n  = wid & 3;
    int co_base = warp_m * 32;

    float acc[2][8][4];
#pragma unroll
    for (int mt = 0; mt < 2; mt++)
#pragma unroll
        for (int nt = 0; nt < 8; nt++)
#pragma unroll
            for (int j = 0; j < 4; j++) acc[mt][nt][j] = 0.f;

    uint32_t b_off = (uint32_t)(((lane & 7) + ((lane >> 4) << 3)) * ROWP * 2)
                   + (uint32_t)(((lane >> 3) & 1) * 16);

    const uint4* afrag_e = (const uint4*)g_w2f
                         + (size_t)e * 9 * (W2F_PER_TAP / 4)
                         + (size_t)warp_m * 512 + lane;

    for (int tap = 0; tap < 9; tap++) {
        int dy = tap / 3, dx = tap % 3;
        const uint4* abase = afrag_e + (size_t)tap * (W2F_PER_TAP / 4);

#pragma unroll
        for (int ks = 0; ks < 4; ks++) {
            uint32_t kso = (uint32_t)(ks * 32);
            uint32_t a_h[2][4], a_l[2][4];
#pragma unroll
            for (int mt = 0; mt < 2; mt++) {
                uint4 vh = abase[((mt * 4 + ks) * 2 + 0) * 32];
                uint4 vl = abase[((mt * 4 + ks) * 2 + 1) * 32];
                a_h[mt][0] = vh.x; a_h[mt][1] = vh.y;
                a_h[mt][2] = vh.z; a_h[mt][3] = vh.w;
                a_l[mt][0] = vl.x; a_l[mt][1] = vl.y;
                a_l[mt][2] = vl.z; a_l[mt][3] = vl.w;
            }
#pragma unroll
            for (int ntp = 0; ntp < 4; ntp++) {
                int y  = warp_n * 4 + ntp;
                uint32_t rrow = (uint32_t)((y + dy) * 18 + dx);
                uint32_t rb   = rrow * (ROWP * 2) + b_off + kso;
                uint32_t bh0, bh1, bh2, bh3, bl0, bl1, bl2, bl3;
                ldsm_x4(bh0, bh1, bh2, bh3, sb + OFF_BH2 + rb);
                ldsm_x4(bl0, bl1, bl2, bl3, sb + OFF_BL2 + rb);
                int nt0 = 2 * ntp, nt1 = 2 * ntp + 1;
                mma16816(acc[0][nt0], a_h[0], bh0, bh1);
                mma16816(acc[1][nt0], a_h[1], bh0, bh1);
                mma16816(acc[0][nt1], a_h[0], bh2, bh3);
                mma16816(acc[1][nt1], a_h[1], bh2, bh3);
                mma16816(acc[0][nt0], a_h[0], bl0, bl1);
                mma16816(acc[1][nt0], a_h[1], bl0, bl1);
                mma16816(acc[0][nt1], a_h[0], bl2, bl3);
                mma16816(acc[1][nt1], a_h[1], bl2, bl3);
                mma16816(acc[0][nt0], a_l[0], bh0, bh1);
                mma16816(acc[1][nt0], a_l[1], bh0, bh1);
                mma16816(acc[0][nt1], a_l[0], bh2, bh3);
                mma16816(acc[1][nt1], a_l[1], bh2, bh3);
            }
        }
    }

    int r  = lane >> 2;
    int c2 = lane & 3;
    float* dstb = g_buf2 + (size_t)b * FCIN;
#pragma unroll
    for (int mt = 0; mt < 2; mt++) {
#pragma unroll
        for (int rg = 0; rg < 2; rg++) {
            int co = co_base + mt * 16 + r + rg * 8;
            float bias = c2b[e * C2 + co];
#pragma unroll
            for (int q = 0; q < 4; q++) {
                int ntp = (q & 1) + (q >> 1) * 4;
                float m = fmaxf(
                    fmaxf(acc[mt][ntp][rg * 2],     acc[mt][ntp][rg * 2 + 1]),
                    fmaxf(acc[mt][ntp + 2][rg * 2], acc[mt][ntp + 2][rg * 2 + 1]));
                int py = warp_n * 2 + (ntp >> 2);
                int px = (ntp & 1) * 4 + c2;
                dstb[co * 64 + py * 8 + px] = fmaxf(m + bias, 0.f);
            }
        }
    }
}

// ---------------- expert FC: blocked GEMM, k-split x4 -> partials ----------
#define FC_SPB    32
#define FC_KCHUNK 128
#define FC_COLH   50
#define FC_KSPL   4
#define FC_KRANGE (FCIN / FC_KSPL)                     // 2048
#define FC_WS_FLOATS (FC_KCHUNK * FC_COLH)             // 6400
#define FC_AS_FLOATS (FC_KCHUNK * FC_SPB)              // 4096
#define FC_SMEM ((FC_WS_FLOATS + FC_AS_FLOATS) * 4)    // 41984 bytes

__global__ void __launch_bounds__(256) fc_kernel(float* __restrict__ dummy)
{
    extern __shared__ float fsm[];
    float* Wsm = fsm;                       // [128][50]
    float* Asm = fsm + FC_WS_FLOATS;        // [128][32]
    __shared__ int sidx[FC_SPB];

    int bi    = blockIdx.x;
    int e     = bi >> 8;                    // 256 blocks per expert
    int rest  = bi & 255;
    int ksp   = rest & 3;                   // k-split id
    int ch    = (rest >> 2) & 1;            // column half
    int chunk = rest >> 3;                  // 0..31
    int n  = g_count[e];
    int s0 = chunk * FC_SPB;
    if (s0 >= n) return;
    int m = n - s0; if (m > FC_SPB) m = FC_SPB;

    int tid = threadIdx.x;
    if (tid < FC_SPB) {
        int idx = s0 + tid; if (idx >= n) idx = n - 1;
        sidx[tid] = g_list[e * B + idx];
    }
    __syncthreads();

    int cg = tid % 25;
    int sg = tid / 25;
    bool act = (sg < 8);

    ull c0[2], c1[2];
#pragma unroll
    for (int p = 0; p < 2; p++) { c0[p] = 0; c1[p] = 0; }

    const float* wsrc_e = g_fwT + (size_t)e * FCIN * NC + ch * FC_COLH;
    int kbeg = ksp * FC_KRANGE;

    for (int k0 = kbeg; k0 < kbeg + FC_KRANGE; k0 += FC_KCHUNK) {
        __syncthreads();
        for (int i = tid; i < FC_KCHUNK * 25; i += 256) {
            int kk = i / 25, c2i = i % 25;
            *(float2*)&Wsm[kk * FC_COLH + c2i * 2] =
                *(const float2*)&wsrc_e[(size_t)(k0 + kk) * NC + c2i * 2];
        }
        for (int i = tid; i < FC_SPB * (FC_KCHUNK / 4); i += 256) {
            int s   = i >> 5;
            int seg = i & 31;
            float4 v = *(const float4*)&g_buf2[(size_t)sidx[s] * FCIN + k0 + seg * 4];
            Asm[(seg * 4 + 0) * FC_SPB + s] = v.x;
            Asm[(seg * 4 + 1) * FC_SPB + s] = v.y;
            Asm[(seg * 4 + 2) * FC_SPB + s] = v.z;
            Asm[(seg * 4 + 3) * FC_SPB + s] = v.w;
        }
        __syncthreads();
        if (act) {
            const float* wp = Wsm + cg * 2;
            const float* ap = Asm + sg * 4;
#pragma unroll 4
            for (int kk = 0; kk < FC_KCHUNK; kk++) {
                float2 w = *(const float2*)(wp + kk * FC_COLH);
                ull ww0 = pk(w.x, w.x);
                ull ww1 = pk(w.y, w.y);
                const ull* arow = (const ull*)(ap + kk * FC_SPB);
#pragma unroll
                for (int p = 0; p < 2; p++) {
                    ull aa = arow[p];
                    c0[p] = ffma2(aa, ww0, c0[p]);
                    c1[p] = ffma2(aa, ww1, c1[p]);
                }
            }
        }
    }

    if (act) {
        int colb = ch * FC_COLH + cg * 2;
        float* part = g_fcp + (size_t)ksp * B * NC;
#pragma unroll
        for (int p = 0; p < 2; p++) {
            float v0lo, v0hi, v1lo, v1hi;
            upk(c0[p], v0lo, v0hi);
            upk(c1[p], v1lo, v1hi);
            int r0 = sg * 4 + 2 * p;
            if (r0 < m) {
                int s = sidx[r0];
                part[(size_t)s * NC + colb]     = v0lo;
                part[(size_t)s * NC + colb + 1] = v1lo;
            }
            if (r0 + 1 < m) {
                int s = sidx[r0 + 1];
                part[(size_t)s * NC + colb]     = v0hi;
                part[(size_t)s * NC + colb + 1] = v1hi;
            }
        }
    }
}

// ---------------- FC reduce: sum 4 partials + bias, scale ----------------
__global__ void fc_reduce_kernel(const float* __restrict__ fb,
                                 float* __restrict__ out)
{
    int i = blockIdx.x * blockDim.x + threadIdx.x;
    if (i >= B * NC) return;
    int s = i / NC;
    int c = i - s * NC;
    float v = ((g_fcp[i] + g_fcp[(size_t)B * NC + i])
            +  (g_fcp[2 * (size_t)B * NC + i] + g_fcp[3 * (size_t)B * NC + i]));
    out[i] = (v + fb[g_bidx[s] * NC + c]) * g_bw[s];
}

// ---------------- launch ----------------
extern "C" void kernel_launch(void* const* d_in, const int* in_sizes, int n_in,
                              void* d_out, int out_size)
{
    const float* x       = (const float*)d_in[0];
    const float* gate_cw = (const float*)d_in[1];
    const float* gate_cb = (const float*)d_in[2];
    const float* gate_fw = (const float*)d_in[3];
    const float* gate_fb = (const float*)d_in[4];
    const float* e_c1w   = (const float*)d_in[5];
    const float* e_c1b   = (const float*)d_in[6];
    const float* e_c2w   = (const float*)d_in[7];
    const float* e_c2b   = (const float*)d_in[8];
    const float* e_fw    = (const float*)d_in[9];
    const float* e_fb    = (const float*)d_in[10];
    float* out = (float*)d_out;

    cudaFuncSetAttribute(conv12_fused_kernel,
                         cudaFuncAttributeMaxDynamicSharedMemorySize, C2_SMEM);
    cudaFuncSetAttribute(fc_kernel,
                         cudaFuncAttributeMaxDynamicSharedMemorySize, FC_SMEM);

    prep_kernel<<<NW2_BLOCKS + NFW_TILES, 256>>>(e_c2w, e_fw);               // 0
    gate_router_kernel<<<B, 256>>>(x, gate_cw, gate_cb, gate_fw, gate_fb,
                                   out + OUT_PROBS_OFF);                     // 1
    conv12_fused_kernel<<<B, 512, C2_SMEM>>>(x, e_c1w, e_c1b, e_c2b);        // 2
    fc_kernel<<<E * 256, 256, FC_SMEM>>>(out);                               // 3 (ncu)
    fc_reduce_kernel<<<(B * NC + 255) / 256, 256>>>(e_fb, out);              // 4
    aux_kernel<<<1, 256>>>(out + OUT_PROBS_OFF, out + OUT_AUX_OFF);          // 5
}

// round 16
// speedup vs baseline: 1.4683x; 1.1844x over previous
#include <cuda_runtime.h>
#include <cuda_fp16.h>
#include <math.h>
#include <cstdint>

// ---------------- problem constants ----------------
#define B     1024
#define CIN   3
#define HW    32
#define GC    16
#define E     4
#define C1    64
#define C2    128
#define NC    100
#define FCIN  8192      // 128*8*8

#define NPIX  324       // 18*18 haloed conv1 output grid
#define ROWP  72        // padded row length (halves); 144B stride

#define OUT_PROBS_OFF (B*NC)
#define OUT_AUX_OFF   (B*NC + B*E)

typedef unsigned long long ull;

// ---- f32x2 helpers ----
__device__ __forceinline__ ull ffma2(ull a, ull b, ull c) {
    ull d;
    asm("fma.rn.f32x2 %0, %1, %2, %3;" : "=l"(d) : "l"(a), "l"(b), "l"(c));
    return d;
}
__device__ __forceinline__ ull pk(float lo, float hi) {
    ull r;
    asm("mov.b64 %0, {%1, %2};" : "=l"(r) : "f"(lo), "f"(hi));
    return r;
}
__device__ __forceinline__ void upk(ull v, float& lo, float& hi) {
    asm("mov.b64 {%0, %1}, %2;" : "=f"(lo), "=f"(hi) : "l"(v));
}

__device__ __forceinline__ uint32_t smem_u32(const void* p) {
    uint32_t a;
    asm("{ .reg .u64 t; cvta.to.shared.u64 t, %1; cvt.u32.u64 %0, t; }"
        : "=r"(a) : "l"(p));
    return a;
}
__device__ __forceinline__ void ldsm_x4(uint32_t& r0, uint32_t& r1,
                                        uint32_t& r2, uint32_t& r3, uint32_t a) {
    asm volatile("ldmatrix.sync.aligned.m8n8.x4.shared.b16 {%0,%1,%2,%3}, [%4];"
                 : "=r"(r0), "=r"(r1), "=r"(r2), "=r"(r3) : "r"(a));
}
__device__ __forceinline__ void mma16816(float* d, const uint32_t* a,
                                         uint32_t b0, uint32_t b1) {
    asm volatile(
        "mma.sync.aligned.m16n8k16.row.col.f32.f16.f16.f32 "
        "{%0,%1,%2,%3}, {%4,%5,%6,%7}, {%8,%9}, {%0,%1,%2,%3};"
        : "+f"(d[0]), "+f"(d[1]), "+f"(d[2]), "+f"(d[3])
        : "r"(a[0]), "r"(a[1]), "r"(a[2]), "r"(a[3]), "r"(b0), "r"(b1));
}

// ---------------- device scratch ----------------
__device__ float    g_buf2[(size_t)B * C2 * 8 * 8];   // conv2+pool out
__device__ float    g_fwT[(size_t)E * FCIN * NC];     // FC weights, [e][k][col]
__device__ float    g_fcp[4 * (size_t)B * NC];        // FC k-split partials
__device__ int      g_bidx[B];
__device__ float    g_bw[B];
__device__ int      g_list[E * B];
__device__ int      g_count[E];
#define W2F_PER_TAP 8192
__device__ uint32_t g_w2f[(size_t)E * 9 * W2F_PER_TAP];

// ---------------- merged prep: w2 fragments + tiled fw transpose ------------
#define NW2_BLOCKS ((E * 9 * W2F_PER_TAP) / 256)      // 1152
#define NFW_TILES  (E * 4 * (FCIN / 32))              // 4096

__global__ void prep_kernel(const float* __restrict__ c2w,
                            const float* __restrict__ fw) {
    int tid = threadIdx.x;
    if (blockIdx.x < NW2_BLOCKS) {
        if (blockIdx.x == 0 && tid < E) g_count[tid] = 0;
        int i = blockIdx.x * 256 + tid;
        int q    = i & 3;
        int lane = (i >> 2) & 31;
        int hl   = (i >> 7) & 1;
        int ks   = (i >> 8) & 3;
        int mt   = (i >> 10) & 1;
        int wm   = (i >> 11) & 3;
        int rest = i >> 13;
        int tap  = rest % 9;
        int e    = rest / 9;

        int row = (lane >> 2) + (q & 1) * 8;
        int kk  = 2 * (lane & 3) + (q >> 1) * 8;
        int co  = wm * 32 + mt * 16 + row;
        int ci  = ks * 16 + kk;

        float v0 = c2w[(((size_t)(e * C2 + co)) * C1 + ci) * 9 + tap];
        float v1 = c2w[(((size_t)(e * C2 + co)) * C1 + ci + 1) * 9 + tap];
        __half h0, h1;
        if (hl == 0) {
            h0 = __float2half_rn(v0);
            h1 = __float2half_rn(v1);
        } else {
            __half t0 = __float2half_rn(v0);
            __half t1 = __float2half_rn(v1);
            h0 = __float2half_rn(v0 - __half2float(t0));
            h1 = __float2half_rn(v1 - __half2float(t1));
        }
        __half2 p = __halves2half2(h0, h1);
        g_w2f[i] = *(uint32_t*)&p;
    } else {
        __shared__ float tile[32][33];
        int t  = blockIdx.x - NW2_BLOCKS;
        int e  = t >> 10;
        int r  = t & 1023;
        int ct = r >> 8;
        int kt = r & 255;
        int tx = tid & 31, ty = tid >> 5;

        const float* src = fw + (size_t)e * NC * FCIN;
        float* dst = g_fwT + (size_t)e * FCIN * NC;
#pragma unroll
        for (int j = 0; j < 4; j++) {
            int c = ct * 32 + ty + j * 8;
            if (c < NC)
                tile[ty + j * 8][tx] = src[(size_t)c * FCIN + kt * 32 + tx];
        }
        __syncthreads();
        int c = ct * 32 + tx;
        if (c < NC) {
#pragma unroll
            for (int j = 0; j < 4; j++) {
                int k = kt * 32 + ty + j * 8;
                dst[(size_t)k * NC + c] = tile[tx][ty + j * 8];
            }
        }
    }
}

// ---------------- gating conv + GAP + router (fused) --------
__global__ void __launch_bounds__(256) gate_router_kernel(
    const float* __restrict__ x, const float* __restrict__ gcw,
    const float* __restrict__ gcb, const float* __restrict__ gfw,
    const float* __restrict__ gfb, float* __restrict__ out_probs)
{
    __shared__ float xs[CIN * 34 * 34];
    __shared__ float wg[GC * 27];
    __shared__ float gb[GC];
    __shared__ float red[256];
    __shared__ float gp16[GC];

    int b   = blockIdx.x;
    int tid = threadIdx.x;

    for (int i = tid; i < CIN * 34 * 34; i += 256) xs[i] = 0.f;
    __syncthreads();
    const float* xb = x + (size_t)b * CIN * HW * HW;
    for (int i = tid; i < CIN * HW * HW; i += 256) {
        int ci = i >> 10, y = (i >> 5) & 31, xx = i & 31;
        xs[(ci * 34 + y + 1) * 34 + xx + 1] = xb[i];
    }
    for (int i = tid; i < GC * 27; i += 256) wg[i] = gcw[i];
    if (tid < GC) gb[tid] = gcb[tid];
    __syncthreads();

    int co = tid >> 4;
    int ln = tid & 15;
    float w[27];
#pragma unroll
    for (int k = 0; k < 27; k++) w[k] = wg[co * 27 + k];
    float bias = gb[co];

    float s = 0.f;
    for (int p = ln; p < HW * HW; p += 16) {
        int y = p >> 5, xx = p & 31;
        float v = bias;
#pragma unroll
        for (int ci = 0; ci < CIN; ci++)
#pragma unroll
            for (int dy = 0; dy < 3; dy++)
#pragma unroll
                for (int dx = 0; dx < 3; dx++)
                    v = fmaf(xs[(ci * 34 + y + dy) * 34 + xx + dx],
                             w[ci * 9 + dy * 3 + dx], v);
        s += fmaxf(v, 0.f);
    }
    red[tid] = s;
    __syncthreads();
    if (ln == 0) {
        float t = 0.f;
#pragma unroll
        for (int j = 0; j < 16; j++) t += red[co * 16 + j];
        gp16[co] = t * (1.f / (HW * HW));
    }
    __syncthreads();

    if (tid == 0) {
        float lg[E];
#pragma unroll
        for (int e = 0; e < E; e++) {
            float v = gfb[e];
#pragma unroll
            for (int k = 0; k < GC; k++) v = fmaf(gp16[k], gfw[e * GC + k], v);
            lg[e] = v;
        }
        float mx = lg[0];
#pragma unroll
        for (int e = 1; e < E; e++) mx = fmaxf(mx, lg[e]);
        float ex[E], se = 0.f;
#pragma unroll
        for (int e = 0; e < E; e++) { ex[e] = expf(lg[e] - mx); se += ex[e]; }
        float inv = 1.f / se;
        float bw = -1.f; int bi = 0;
#pragma unroll
        for (int e = 0; e < E; e++) {
            float p = ex[e] * inv;
            out_probs[b * E + e] = p;
            if (p > bw) { bw = p; bi = e; }
        }
        g_bidx[b] = bi;
        g_bw[b]   = bw;
        int pos = atomicAdd(&g_count[bi], 1);
        g_list[bi * B + pos] = b;
    }
}

// ---------------- fused conv1 + conv2 (A fragments direct from gmem) -------
#define OFF_BH2   0
#define OFF_BL2   (NPIX * ROWP * 2)                 // 46656
#define OFF_XS    (2 * NPIX * ROWP * 2)             // 93312
#define C2_SMEM   (OFF_XS + CIN * 34 * 34 * 4)      // 107184

__global__ void __launch_bounds__(512, 1) conv12_fused_kernel(
    const float* __restrict__ x, const float* __restrict__ c1w,
    const float* __restrict__ c1b, const float* __restrict__ c2b)
{
    extern __shared__ char smem[];
    __shared__ float ws[C1 * 27];
    __shared__ float bs[C1];
    uint32_t sb = smem_u32(smem);

    int b    = blockIdx.x;
    int tid  = threadIdx.x;
    int wid  = tid >> 5;
    int lane = tid & 31;
    int e    = g_bidx[b];

    float* xs = (float*)(smem + OFF_XS);

    {
        uint32_t* bz = (uint32_t*)(smem + OFF_BH2);
        for (int i = tid; i < NPIX * ROWP; i += 512) bz[i] = 0;
        for (int i = tid; i < CIN * 34 * 34; i += 512) xs[i] = 0.f;
    }
    __syncthreads();
    {
        const float* xb = x + (size_t)b * CIN * HW * HW;
        for (int i = tid; i < CIN * HW * HW; i += 512) {
            int ci = i >> 10, y = (i >> 5) & 31, xx = i & 31;
            xs[(ci * 34 + y + 1) * 34 + xx + 1] = xb[i];
        }
        const float* wsrc = c1w + (size_t)e * C1 * 27;
        for (int i = tid; i < C1 * 27; i += 512) ws[i] = wsrc[i];
        if (tid < C1) bs[tid] = c1b[e * C1 + tid];
    }
    __syncthreads();

    {
        int co  = tid >> 3;
        int oct = tid & 7;
        float wr[27];
#pragma unroll
        for (int k = 0; k < 27; k++) wr[k] = ws[co * 27 + k];
        float bias = bs[co];
        ull bias2 = pk(bias, bias);
        __half* BHp = (__half*)(smem + OFF_BH2);
        __half* BLp = (__half*)(smem + OFF_BL2);

        for (int pr = 0; pr < 2; pr++) {
            int py = oct * 2 + pr;
            int Y  = 2 * py;
            for (int pg = 0; pg < 2; pg++) {
                ull acc0[8], acc1[8];
#pragma unroll
                for (int j = 0; j < 8; j++) { acc0[j] = bias2; acc1[j] = bias2; }
#pragma unroll
                for (int ci = 0; ci < CIN; ci++) {
                    ull w2[9];
#pragma unroll
                    for (int k = 0; k < 9; k++) w2[k] = pk(wr[ci * 9 + k], wr[ci * 9 + k]);
#pragma unroll
                    for (int j = 0; j < 8; j++) {
                        int X = 2 * (pg * 8 + j);
                        const float* base = &xs[(ci * 34 + Y) * 34 + X];
                        ull q[4][3];
#pragma unroll
                        for (int r = 0; r < 4; r++) {
                            float2 ra = *(const float2*)(base + r * 34);
                            float2 rb = *(const float2*)(base + r * 34 + 2);
                            q[r][0] = pk(ra.x, ra.y);
                            q[r][1] = pk(ra.y, rb.x);
                            q[r][2] = pk(rb.x, rb.y);
                        }
#pragma unroll
                        for (int dy = 0; dy < 3; dy++)
#pragma unroll
                            for (int dxj = 0; dxj < 3; dxj++) {
                                acc0[j] = ffma2(q[dy][dxj],     w2[dy * 3 + dxj], acc0[j]);
                                acc1[j] = ffma2(q[dy + 1][dxj], w2[dy * 3 + dxj], acc1[j]);
                            }
                    }
                }
#pragma unroll
                for (int j = 0; j < 8; j++) {
                    int px = pg * 8 + j;
                    float a00, a01, a10, a11;
                    upk(acc0[j], a00, a01);
                    upk(acc1[j], a10, a11);
                    float v = fmaxf(fmaxf(fmaxf(a00, a01), fmaxf(a10, a11)), 0.f);
                    __half h = __float2half_rn(v);
                    int pix = (py + 1) * 18 + (px + 1);
                    BHp[pix * ROWP + co] = h;
                    BLp[pix * ROWP + co] = __float2half_rn(v - __half2float(h));
                }
            }
        }
    }
    __syncthreads();

    int warp_m  = wid >> 2;
    int warp_n  = wid & 3;
    int co_base = warp_m * 32;

    float acc[2][8][4];
#pragma unroll
    for (int mt = 0; mt < 2; mt++)
#pragma unroll
        for (int nt = 0; nt < 8; nt++)
#pragma unroll
            for (int j = 0; j < 4; j++) acc[mt][nt][j] = 0.f;

    uint32_t b_off = (uint32_t)(((lane & 7) + ((lane >> 4) << 3)) * ROWP * 2)
                   + (uint32_t)(((lane >> 3) & 1) * 16);

    const uint4* afrag_e = (const uint4*)g_w2f
                         + (size_t)e * 9 * (W2F_PER_TAP / 4)
                         + (size_t)warp_m * 512 + lane;

    for (int tap = 0; tap < 9; tap++) {
        int dy = tap / 3, dx = tap % 3;
        const uint4* abase = afrag_e + (size_t)tap * (W2F_PER_TAP / 4);

#pragma unroll
        for (int ks = 0; ks < 4; ks++) {
            uint32_t kso = (uint32_t)(ks * 32);
            uint32_t a_h[2][4], a_l[2][4];
#pragma unroll
            for (int mt = 0; mt < 2; mt++) {
                uint4 vh = abase[((mt * 4 + ks) * 2 + 0) * 32];
                uint4 vl = abase[((mt * 4 + ks) * 2 + 1) * 32];
                a_h[mt][0] = vh.x; a_h[mt][1] = vh.y;
                a_h[mt][2] = vh.z; a_h[mt][3] = vh.w;
                a_l[mt][0] = vl.x; a_l[mt][1] = vl.y;
                a_l[mt][2] = vl.z; a_l[mt][3] = vl.w;
            }
#pragma unroll
            for (int ntp = 0; ntp < 4; ntp++) {
                int y  = warp_n * 4 + ntp;
                uint32_t rrow = (uint32_t)((y + dy) * 18 + dx);
                uint32_t rb   = rrow * (ROWP * 2) + b_off + kso;
                uint32_t bh0, bh1, bh2, bh3, bl0, bl1, bl2, bl3;
                ldsm_x4(bh0, bh1, bh2, bh3, sb + OFF_BH2 + rb);
                ldsm_x4(bl0, bl1, bl2, bl3, sb + OFF_BL2 + rb);
                int nt0 = 2 * ntp, nt1 = 2 * ntp + 1;
                mma16816(acc[0][nt0], a_h[0], bh0, bh1);
                mma16816(acc[1][nt0], a_h[1], bh0, bh1);
                mma16816(acc[0][nt1], a_h[0], bh2, bh3);
                mma16816(acc[1][nt1], a_h[1], bh2, bh3);
                mma16816(acc[0][nt0], a_h[0], bl0, bl1);
                mma16816(acc[1][nt0], a_h[1], bl0, bl1);
                mma16816(acc[0][nt1], a_h[0], bl2, bl3);
                mma16816(acc[1][nt1], a_h[1], bl2, bl3);
                mma16816(acc[0][nt0], a_l[0], bh0, bh1);
                mma16816(acc[1][nt0], a_l[1], bh0, bh1);
                mma16816(acc[0][nt1], a_l[0], bh2, bh3);
                mma16816(acc[1][nt1], a_l[1], bh2, bh3);
            }
        }
    }

    int r  = lane >> 2;
    int c2 = lane & 3;
    float* dstb = g_buf2 + (size_t)b * FCIN;
#pragma unroll
    for (int mt = 0; mt < 2; mt++) {
#pragma unroll
        for (int rg = 0; rg < 2; rg++) {
            int co = co_base + mt * 16 + r + rg * 8;
            float bias = c2b[e * C2 + co];
#pragma unroll
            for (int q = 0; q < 4; q++) {
                int ntp = (q & 1) + (q >> 1) * 4;
                float m = fmaxf(
                    fmaxf(acc[mt][ntp][rg * 2],     acc[mt][ntp][rg * 2 + 1]),
                    fmaxf(acc[mt][ntp + 2][rg * 2], acc[mt][ntp + 2][rg * 2 + 1]));
                int py = warp_n * 2 + (ntp >> 2);
                int px = (ntp & 1) * 4 + c2;
                dstb[co * 64 + py * 8 + px] = fmaxf(m + bias, 0.f);
            }
        }
    }
}

// ---------------- expert FC: blocked GEMM, k-split x4, conflict-free smem ---
#define FC_SPB    32
#define FC_KCHUNK 128
#define FC_COLH   50
#define FC_KSPL   4
#define FC_KRANGE (FCIN / FC_KSPL)                     // 2048
#define FC_AROW   132                                  // padded act row (floats)
#define FC_WS_FLOATS (FC_KCHUNK * FC_COLH)             // 6400
#define FC_AS_FLOATS (FC_SPB * FC_AROW)                // 4224
#define FC_SMEM ((FC_WS_FLOATS + FC_AS_FLOATS) * 4)    // 42496 bytes

__global__ void __launch_bounds__(256) fc_kernel(float* __restrict__ dummy)
{
    extern __shared__ float fsm[];
    float* Wsm = fsm;                       // [128][50]
    float* Asm = fsm + FC_WS_FLOATS;        // [32][132] row-major
    __shared__ int sidx[FC_SPB];

    int bi    = blockIdx.x;
    int e     = bi >> 8;
    int rest  = bi & 255;
    int ksp   = rest & 3;
    int ch    = (rest >> 2) & 1;
    int chunk = rest >> 3;
    int n  = g_count[e];
    int s0 = chunk * FC_SPB;
    if (s0 >= n) return;
    int m = n - s0; if (m > FC_SPB) m = FC_SPB;

    int tid = threadIdx.x;
    if (tid < FC_SPB) {
        int idx = s0 + tid; if (idx >= n) idx = n - 1;
        sidx[tid] = g_list[e * B + idx];
    }
    __syncthreads();

    int cg = tid % 25;                 // col pair 0..24
    int sg = tid / 25;                 // 0..9; active if <8 (4 samples each)
    bool act = (sg < 8);

    ull c[4];                          // per sample: (col c, col c+1)
#pragma unroll
    for (int p = 0; p < 4; p++) c[p] = 0;

    const float* wsrc_e = g_fwT + (size_t)e * FCIN * NC + ch * FC_COLH;
    int kbeg = ksp * FC_KRANGE;

    for (int k0 = kbeg; k0 < kbeg + FC_KRANGE; k0 += FC_KCHUNK) {
        __syncthreads();
        // stage weights [kk][50]
        for (int i = tid; i < FC_KCHUNK * 25; i += 256) {
            int kk = i / 25, c2i = i % 25;
            *(float2*)&Wsm[kk * FC_COLH + c2i * 2] =
                *(const float2*)&wsrc_e[(size_t)(k0 + kk) * NC + c2i * 2];
        }
        // stage activations row-major [s][kk] (coalesced, conflict-free)
        for (int i = tid; i < FC_SPB * (FC_KCHUNK / 4); i += 256) {
            int s   = i >> 5;
            int seg = i & 31;
            float4 v = *(const float4*)&g_buf2[(size_t)sidx[s] * FCIN + k0 + seg * 4];
            *(float4*)&Asm[s * FC_AROW + seg * 4] = v;
        }
        __syncthreads();
        if (act) {
            const float* wp = Wsm + cg * 2;
            const float* a0 = Asm + (sg * 4 + 0) * FC_AROW;
            const float* a1 = Asm + (sg * 4 + 1) * FC_AROW;
            const float* a2 = Asm + (sg * 4 + 2) * FC_AROW;
            const float* a3 = Asm + (sg * 4 + 3) * FC_AROW;
#pragma unroll 4
            for (int kk = 0; kk < FC_KCHUNK; kk++) {
                ull wab = *(const ull*)(wp + kk * FC_COLH);   // (col, col+1)
                c[0] = ffma2(pk(a0[kk], a0[kk]), wab, c[0]);
                c[1] = ffma2(pk(a1[kk], a1[kk]), wab, c[1]);
                c[2] = ffma2(pk(a2[kk], a2[kk]), wab, c[2]);
                c[3] = ffma2(pk(a3[kk], a3[kk]), wab, c[3]);
            }
        }
    }

    if (act) {
        int colb = ch * FC_COLH + cg * 2;
        float* part = g_fcp + (size_t)ksp * B * NC;
#pragma unroll
        for (int p = 0; p < 4; p++) {
            int rr = sg * 4 + p;
            if (rr < m) {
                int s = sidx[rr];
                float lo, hi;
                upk(c[p], lo, hi);
                part[(size_t)s * NC + colb]     = lo;
                part[(size_t)s * NC + colb + 1] = hi;
            }
        }
    }
}

// ---------------- FC reduce + aux loss (merged) ----------------
#define NRED_BLOCKS ((B * NC + 255) / 256)
__global__ void reduce_aux_kernel(const float* __restrict__ fb,
                                  const float* __restrict__ probs,
                                  float* __restrict__ out)
{
    if (blockIdx.x < NRED_BLOCKS) {
        int i = blockIdx.x * 256 + threadIdx.x;
        if (i >= B * NC) return;
        int s = i / NC;
        int c = i - s * NC;
        float v = ((g_fcp[i] + g_fcp[(size_t)B * NC + i])
                +  (g_fcp[2 * (size_t)B * NC + i] + g_fcp[3 * (size_t)B * NC + i]));
        out[i] = (v + fb[g_bidx[s] * NC + c]) * g_bw[s];
    } else {
        __shared__ float sm[256 * E];
        int tid = threadIdx.x;
        float s[E] = {0.f, 0.f, 0.f, 0.f};
        for (int i = tid; i < B; i += 256) {
#pragma unroll
            for (int e = 0; e < E; e++) s[e] += probs[i * E + e];
        }
#pragma unroll
        for (int e = 0; e < E; e++) sm[tid * E + e] = s[e];
        __syncthreads();
        for (int st = 128; st > 0; st >>= 1) {
            if (tid < st)
#pragma unroll
                for (int e = 0; e < E; e++) sm[tid * E + e] += sm[(tid + st) * E + e];
            __syncthreads();
        }
        if (tid == 0) {
            float a = 0.f;
#pragma unroll
            for (int e = 0; e < E; e++) {
                float m = sm[e] * (1.f / B) - 1.f / E;
                a += m * m;
            }
            out[OUT_AUX_OFF] = a * (1.f / E);
        }
    }
}

// ---------------- launch ----------------
extern "C" void kernel_launch(void* const* d_in, const int* in_sizes, int n_in,
                              void* d_out, int out_size)
{
    const float* x       = (const float*)d_in[0];
    const float* gate_cw = (const float*)d_in[1];
    const float* gate_cb = (const float*)d_in[2];
    const float* gate_fw = (const float*)d_in[3];
    const float* gate_fb = (const float*)d_in[4];
    const float* e_c1w   = (const float*)d_in[5];
    const float* e_c1b   = (const float*)d_in[6];
    const float* e_c2w   = (const float*)d_in[7];
    const float* e_c2b   = (const float*)d_in[8];
    const float* e_fw    = (const float*)d_in[9];
    const float* e_fb    = (const float*)d_in[10];
    float* out = (float*)d_out;

    cudaFuncSetAttribute(conv12_fused_kernel,
                         cudaFuncAttributeMaxDynamicSharedMemorySize, C2_SMEM);
    cudaFuncSetAttribute(fc_kernel,
                         cudaFuncAttributeMaxDynamicSharedMemorySize, FC_SMEM);

    prep_kernel<<<NW2_BLOCKS + NFW_TILES, 256>>>(e_c2w, e_fw);               // 0
    gate_router_kernel<<<B, 256>>>(x, gate_cw, gate_cb, gate_fw, gate_fb,
                                   out + OUT_PROBS_OFF);                     // 1
    conv12_fused_kernel<<<B, 512, C2_SMEM>>>(x, e_c1w, e_c1b, e_c2b);        // 2
    fc_kernel<<<E * 256, 256, FC_SMEM>>>(out);                               // 3 (ncu)
    reduce_aux_kernel<<<NRED_BLOCKS + 1, 256>>>(e_fb, out + OUT_PROBS_OFF,
                                                out);                        // 4
}

// round 17
// speedup vs baseline: 1.6822x; 1.1456x over previous
#include <cuda_runtime.h>
#include <cuda_fp16.h>
#include <math.h>
#include <cstdint>

// ---------------- problem constants ----------------
#define B     1024
#define CIN   3
#define HW    32
#define GC    16
#define E     4
#define C1    64
#define C2    128
#define NC    100
#define FCIN  8192      // 128*8*8

#define NPIX  324       // 18*18 haloed conv1 output grid
#define ROWP  72        // padded row length (halves); 144B stride

#define OUT_PROBS_OFF (B*NC)
#define OUT_AUX_OFF   (B*NC + B*E)

typedef unsigned long long ull;

// ---- f32x2 helpers ----
__device__ __forceinline__ ull ffma2(ull a, ull b, ull c) {
    ull d;
    asm("fma.rn.f32x2 %0, %1, %2, %3;" : "=l"(d) : "l"(a), "l"(b), "l"(c));
    return d;
}
__device__ __forceinline__ ull pk(float lo, float hi) {
    ull r;
    asm("mov.b64 %0, {%1, %2};" : "=l"(r) : "f"(lo), "f"(hi));
    return r;
}
__device__ __forceinline__ void upk(ull v, float& lo, float& hi) {
    asm("mov.b64 {%0, %1}, %2;" : "=f"(lo), "=f"(hi) : "l"(v));
}

__device__ __forceinline__ uint32_t smem_u32(const void* p) {
    uint32_t a;
    asm("{ .reg .u64 t; cvta.to.shared.u64 t, %1; cvt.u32.u64 %0, t; }"
        : "=r"(a) : "l"(p));
    return a;
}
__device__ __forceinline__ void ldsm_x4(uint32_t& r0, uint32_t& r1,
                                        uint32_t& r2, uint32_t& r3, uint32_t a) {
    asm volatile("ldmatrix.sync.aligned.m8n8.x4.shared.b16 {%0,%1,%2,%3}, [%4];"
                 : "=r"(r0), "=r"(r1), "=r"(r2), "=r"(r3) : "r"(a));
}
__device__ __forceinline__ void mma16816(float* d, const uint32_t* a,
                                         uint32_t b0, uint32_t b1) {
    asm volatile(
        "mma.sync.aligned.m16n8k16.row.col.f32.f16.f16.f32 "
        "{%0,%1,%2,%3}, {%4,%5,%6,%7}, {%8,%9}, {%0,%1,%2,%3};"
        : "+f"(d[0]), "+f"(d[1]), "+f"(d[2]), "+f"(d[3])
        : "r"(a[0]), "r"(a[1]), "r"(a[2]), "r"(a[3]), "r"(b0), "r"(b1));
}

// ---------------- device scratch ----------------
__device__ float    g_buf2[(size_t)B * C2 * 8 * 8];   // conv2+pool out
__device__ float    g_fwT[(size_t)E * FCIN * NC];     // FC weights, [e][k][col]
__device__ float    g_fcp[8 * (size_t)B * NC];        // FC k-split partials
__device__ int      g_bidx[B];
__device__ float    g_bw[B];
__device__ int      g_list[E * B];
__device__ int      g_count[E];
#define W2F_PER_TAP 8192
__device__ uint32_t g_w2f[(size_t)E * 9 * W2F_PER_TAP];

// ---------------- merged prep: w2 fragments + tiled fw transpose ------------
#define NW2_BLOCKS ((E * 9 * W2F_PER_TAP) / 256)      // 1152
#define NFW_TILES  (E * 4 * (FCIN / 32))              // 4096

__global__ void prep_kernel(const float* __restrict__ c2w,
                            const float* __restrict__ fw) {
    int tid = threadIdx.x;
    if (blockIdx.x < NW2_BLOCKS) {
        if (blockIdx.x == 0 && tid < E) g_count[tid] = 0;
        int i = blockIdx.x * 256 + tid;
        int q    = i & 3;
        int lane = (i >> 2) & 31;
        int hl   = (i >> 7) & 1;
        int ks   = (i >> 8) & 3;
        int mt   = (i >> 10) & 1;
        int wm   = (i >> 11) & 3;
        int rest = i >> 13;
        int tap  = rest % 9;
        int e    = rest / 9;

        int row = (lane >> 2) + (q & 1) * 8;
        int kk  = 2 * (lane & 3) + (q >> 1) * 8;
        int co  = wm * 32 + mt * 16 + row;
        int ci  = ks * 16 + kk;

        float v0 = c2w[(((size_t)(e * C2 + co)) * C1 + ci) * 9 + tap];
        float v1 = c2w[(((size_t)(e * C2 + co)) * C1 + ci + 1) * 9 + tap];
        __half h0, h1;
        if (hl == 0) {
            h0 = __float2half_rn(v0);
            h1 = __float2half_rn(v1);
        } else {
            __half t0 = __float2half_rn(v0);
            __half t1 = __float2half_rn(v1);
            h0 = __float2half_rn(v0 - __half2float(t0));
            h1 = __float2half_rn(v1 - __half2float(t1));
        }
        __half2 p = __halves2half2(h0, h1);
        g_w2f[i] = *(uint32_t*)&p;
    } else {
        __shared__ float tile[32][33];
        int t  = blockIdx.x - NW2_BLOCKS;
        int e  = t >> 10;
        int r  = t & 1023;
        int ct = r >> 8;
        int kt = r & 255;
        int tx = tid & 31, ty = tid >> 5;

        const float* src = fw + (size_t)e * NC * FCIN;
        float* dst = g_fwT + (size_t)e * FCIN * NC;
#pragma unroll
        for (int j = 0; j < 4; j++) {
            int c = ct * 32 + ty + j * 8;
            if (c < NC)
                tile[ty + j * 8][tx] = src[(size_t)c * FCIN + kt * 32 + tx];
        }
        __syncthreads();
        int c = ct * 32 + tx;
        if (c < NC) {
#pragma unroll
            for (int j = 0; j < 4; j++) {
                int k = kt * 32 + ty + j * 8;
                dst[(size_t)k * NC + c] = tile[tx][ty + j * 8];
            }
        }
    }
}

// ---------------- gating conv + GAP + router (fused) --------
__global__ void __launch_bounds__(256) gate_router_kernel(
    const float* __restrict__ x, const float* __restrict__ gcw,
    const float* __restrict__ gcb, const float* __restrict__ gfw,
    const float* __restrict__ gfb, float* __restrict__ out_probs)
{
    __shared__ float xs[CIN * 34 * 34];
    __shared__ float wg[GC * 27];
    __shared__ float gb[GC];
    __shared__ float red[256];
    __shared__ float gp16[GC];

    int b   = blockIdx.x;
    int tid = threadIdx.x;

    for (int i = tid; i < CIN * 34 * 34; i += 256) xs[i] = 0.f;
    __syncthreads();
    const float* xb = x + (size_t)b * CIN * HW * HW;
    for (int i = tid; i < CIN * HW * HW; i += 256) {
        int ci = i >> 10, y = (i >> 5) & 31, xx = i & 31;
        xs[(ci * 34 + y + 1) * 34 + xx + 1] = xb[i];
    }
    for (int i = tid; i < GC * 27; i += 256) wg[i] = gcw[i];
    if (tid < GC) gb[tid] = gcb[tid];
    __syncthreads();

    int co = tid >> 4;
    int ln = tid & 15;
    float w[27];
#pragma unroll
    for (int k = 0; k < 27; k++) w[k] = wg[co * 27 + k];
    float bias = gb[co];

    float s = 0.f;
    for (int p = ln; p < HW * HW; p += 16) {
        int y = p >> 5, xx = p & 31;
        float v = bias;
#pragma unroll
        for (int ci = 0; ci < CIN; ci++)
#pragma unroll
            for (int dy = 0; dy < 3; dy++)
#pragma unroll
                for (int dx = 0; dx < 3; dx++)
                    v = fmaf(xs[(ci * 34 + y + dy) * 34 + xx + dx],
                             w[ci * 9 + dy * 3 + dx], v);
        s += fmaxf(v, 0.f);
    }
    red[tid] = s;
    __syncthreads();
    if (ln == 0) {
        float t = 0.f;
#pragma unroll
        for (int j = 0; j < 16; j++) t += red[co * 16 + j];
        gp16[co] = t * (1.f / (HW * HW));
    }
    __syncthreads();

    if (tid == 0) {
        float lg[E];
#pragma unroll
        for (int e = 0; e < E; e++) {
            float v = gfb[e];
#pragma unroll
            for (int k = 0; k < GC; k++) v = fmaf(gp16[k], gfw[e * GC + k], v);
            lg[e] = v;
        }
        float mx = lg[0];
#pragma unroll
        for (int e = 1; e < E; e++) mx = fmaxf(mx, lg[e]);
        float ex[E], se = 0.f;
#pragma unroll
        for (int e = 0; e < E; e++) { ex[e] = expf(lg[e] - mx); se += ex[e]; }
        float inv = 1.f / se;
        float bw = -1.f; int bi = 0;
#pragma unroll
        for (int e = 0; e < E; e++) {
            float p = ex[e] * inv;
            out_probs[b * E + e] = p;
            if (p > bw) { bw = p; bi = e; }
        }
        g_bidx[b] = bi;
        g_bw[b]   = bw;
        int pos = atomicAdd(&g_count[bi], 1);
        g_list[bi * B + pos] = b;
    }
}

// ---------------- fused conv1 + conv2 (A fragments direct from gmem) -------
#define OFF_BH2   0
#define OFF_BL2   (NPIX * ROWP * 2)                 // 46656
#define OFF_XS    (2 * NPIX * ROWP * 2)             // 93312
#define C2_SMEM   (OFF_XS + CIN * 34 * 34 * 4)      // 107184

__global__ void __launch_bounds__(512, 1) conv12_fused_kernel(
    const float* __restrict__ x, const float* __restrict__ c1w,
    const float* __restrict__ c1b, const float* __restrict__ c2b)
{
    extern __shared__ char smem[];
    __shared__ float ws[C1 * 27];
    __shared__ float bs[C1];
    uint32_t sb = smem_u32(smem);

    int b    = blockIdx.x;
    int tid  = threadIdx.x;
    int wid  = tid >> 5;
    int lane = tid & 31;
    int e    = g_bidx[b];

    float* xs = (float*)(smem + OFF_XS);

    {
        uint32_t* bz = (uint32_t*)(smem + OFF_BH2);
        for (int i = tid; i < NPIX * ROWP; i += 512) bz[i] = 0;
        for (int i = tid; i < CIN * 34 * 34; i += 512) xs[i] = 0.f;
    }
    __syncthreads();
    {
        const float* xb = x + (size_t)b * CIN * HW * HW;
        for (int i = tid; i < CIN * HW * HW; i += 512) {
            int ci = i >> 10, y = (i >> 5) & 31, xx = i & 31;
            xs[(ci * 34 + y + 1) * 34 + xx + 1] = xb[i];
        }
        const float* wsrc = c1w + (size_t)e * C1 * 27;
        for (int i = tid; i < C1 * 27; i += 512) ws[i] = wsrc[i];
        if (tid < C1) bs[tid] = c1b[e * C1 + tid];
    }
    __syncthreads();

    {
        int co  = tid >> 3;
        int oct = tid & 7;
        float wr[27];
#pragma unroll
        for (int k = 0; k < 27; k++) wr[k] = ws[co * 27 + k];
        float bias = bs[co];
        ull bias2 = pk(bias, bias);
        __half* BHp = (__half*)(smem + OFF_BH2);
        __half* BLp = (__half*)(smem + OFF_BL2);

        for (int pr = 0; pr < 2; pr++) {
            int py = oct * 2 + pr;
            int Y  = 2 * py;
            for (int pg = 0; pg < 2; pg++) {
                ull acc0[8], acc1[8];
#pragma unroll
                for (int j = 0; j < 8; j++) { acc0[j] = bias2; acc1[j] = bias2; }
#pragma unroll
                for (int ci = 0; ci < CIN; ci++) {
                    ull w2[9];
#pragma unroll
                    for (int k = 0; k < 9; k++) w2[k] = pk(wr[ci * 9 + k], wr[ci * 9 + k]);
#pragma unroll
                    for (int j = 0; j < 8; j++) {
                        int X = 2 * (pg * 8 + j);
                        const float* base = &xs[(ci * 34 + Y) * 34 + X];
                        ull q[4][3];
#pragma unroll
                        for (int r = 0; r < 4; r++) {
                            float2 ra = *(const float2*)(base + r * 34);
                            float2 rb = *(const float2*)(base + r * 34 + 2);
                            q[r][0] = pk(ra.x, ra.y);
                            q[r][1] = pk(ra.y, rb.x);
                            q[r][2] = pk(rb.x, rb.y);
                        }
#pragma unroll
                        for (int dy = 0; dy < 3; dy++)
#pragma unroll
                            for (int dxj = 0; dxj < 3; dxj++) {
                                acc0[j] = ffma2(q[dy][dxj],     w2[dy * 3 + dxj], acc0[j]);
                                acc1[j] = ffma2(q[dy + 1][dxj], w2[dy * 3 + dxj], acc1[j]);
                            }
                    }
                }
#pragma unroll
                for (int j = 0; j < 8; j++) {
                    int px = pg * 8 + j;
                    float a00, a01, a10, a11;
                    upk(acc0[j], a00, a01);
                    upk(acc1[j], a10, a11);
                    float v = fmaxf(fmaxf(fmaxf(a00, a01), fmaxf(a10, a11)), 0.f);
                    __half h = __float2half_rn(v);
                    int pix = (py + 1) * 18 + (px + 1);
                    BHp[pix * ROWP + co] = h;
                    BLp[pix * ROWP + co] = __float2half_rn(v - __half2float(h));
                }
            }
        }
    }
    __syncthreads();

    int warp_m  = wid >> 2;
    int warp_n  = wid & 3;
    int co_base = warp_m * 32;

    float acc[2][8][4];
#pragma unroll
    for (int mt = 0; mt < 2; mt++)
#pragma unroll
        for (int nt = 0; nt < 8; nt++)
#pragma unroll
            for (int j = 0; j < 4; j++) acc[mt][nt][j] = 0.f;

    uint32_t b_off = (uint32_t)(((lane & 7) + ((lane >> 4) << 3)) * ROWP * 2)
                   + (uint32_t)(((lane >> 3) & 1) * 16);

    const uint4* afrag_e = (const uint4*)g_w2f
                         + (size_t)e * 9 * (W2F_PER_TAP / 4)
                         + (size_t)warp_m * 512 + lane;

    for (int tap = 0; tap < 9; tap++) {
        int dy = tap / 3, dx = tap % 3;
        const uint4* abase = afrag_e + (size_t)tap * (W2F_PER_TAP / 4);

#pragma unroll
        for (int ks = 0; ks < 4; ks++) {
            uint32_t kso = (uint32_t)(ks * 32);
            uint32_t a_h[2][4], a_l[2][4];
#pragma unroll
            for (int mt = 0; mt < 2; mt++) {
                uint4 vh = abase[((mt * 4 + ks) * 2 + 0) * 32];
                uint4 vl = abase[((mt * 4 + ks) * 2 + 1) * 32];
                a_h[mt][0] = vh.x; a_h[mt][1] = vh.y;
                a_h[mt][2] = vh.z; a_h[mt][3] = vh.w;
                a_l[mt][0] = vl.x; a_l[mt][1] = vl.y;
                a_l[mt][2] = vl.z; a_l[mt][3] = vl.w;
            }
#pragma unroll
            for (int ntp = 0; ntp < 4; ntp++) {
                int y  = warp_n * 4 + ntp;
                uint32_t rrow = (uint32_t)((y + dy) * 18 + dx);
                uint32_t rb   = rrow * (ROWP * 2) + b_off + kso;
                uint32_t bh0, bh1, bh2, bh3, bl0, bl1, bl2, bl3;
                ldsm_x4(bh0, bh1, bh2, bh3, sb + OFF_BH2 + rb);
                ldsm_x4(bl0, bl1, bl2, bl3, sb + OFF_BL2 + rb);
                int nt0 = 2 * ntp, nt1 = 2 * ntp + 1;
                mma16816(acc[0][nt0], a_h[0], bh0, bh1);
                mma16816(acc[1][nt0], a_h[1], bh0, bh1);
                mma16816(acc[0][nt1], a_h[0], bh2, bh3);
                mma16816(acc[1][nt1], a_h[1], bh2, bh3);
                mma16816(acc[0][nt0], a_h[0], bl0, bl1);
                mma16816(acc[1][nt0], a_h[1], bl0, bl1);
                mma16816(acc[0][nt1], a_h[0], bl2, bl3);
                mma16816(acc[1][nt1], a_h[1], bl2, bl3);
                mma16816(acc[0][nt0], a_l[0], bh0, bh1);
                mma16816(acc[1][nt0], a_l[1], bh0, bh1);
                mma16816(acc[0][nt1], a_l[0], bh2, bh3);
                mma16816(acc[1][nt1], a_l[1], bh2, bh3);
            }
        }
    }

    int r  = lane >> 2;
    int c2 = lane & 3;
    float* dstb = g_buf2 + (size_t)b * FCIN;
#pragma unroll
    for (int mt = 0; mt < 2; mt++) {
#pragma unroll
        for (int rg = 0; rg < 2; rg++) {
            int co = co_base + mt * 16 + r + rg * 8;
            float bias = c2b[e * C2 + co];
#pragma unroll
            for (int q = 0; q < 4; q++) {
                int ntp = (q & 1) + (q >> 1) * 4;
                float m = fmaxf(
                    fmaxf(acc[mt][ntp][rg * 2],     acc[mt][ntp][rg * 2 + 1]),
                    fmaxf(acc[mt][ntp + 2][rg * 2], acc[mt][ntp + 2][rg * 2 + 1]));
                int py = warp_n * 2 + (ntp >> 2);
                int px = (ntp & 1) * 4 + c2;
                dstb[co * 64 + py * 8 + px] = fmaxf(m + bias, 0.f);
            }
        }
    }
}

// ---------------- expert FC: blocked GEMM, k-split x8, double-buffered -----
#define FC_SPB    32
#define FC_KCHUNK 128
#define FC_COLH   50
#define FC_KSPL   8
#define FC_KRANGE (FCIN / FC_KSPL)                     // 1024
#define FC_NCH    (FC_KRANGE / FC_KCHUNK)              // 8 chunks
#define FC_AROW   132
#define FC_WS_FLOATS (FC_KCHUNK * FC_COLH)             // 6400
#define FC_AS_FLOATS (FC_SPB * FC_AROW)                // 4224
#define FC_BUF_FLOATS (FC_WS_FLOATS + FC_AS_FLOATS)    // 10624
#define FC_SMEM (2 * FC_BUF_FLOATS * 4)                // 84992 bytes

__global__ void __launch_bounds__(256) fc_kernel(float* __restrict__ dummy)
{
    extern __shared__ float fsm[];
    __shared__ int sidx[FC_SPB];

    int bi    = blockIdx.x;
    int e     = bi >> 9;                    // 512 blocks per expert
    int rest  = bi & 511;
    int ksp   = rest & 7;                   // k-split id (8)
    int ch    = (rest >> 3) & 1;            // column half
    int chunk = rest >> 4;                  // 0..31
    int n  = g_count[e];
    int s0 = chunk * FC_SPB;
    if (s0 >= n) return;
    int m = n - s0; if (m > FC_SPB) m = FC_SPB;

    int tid = threadIdx.x;
    if (tid < FC_SPB) {
        int idx = s0 + tid; if (idx >= n) idx = n - 1;
        sidx[tid] = g_list[e * B + idx];
    }
    __syncthreads();

    int cg = tid % 25;
    int sg = tid / 25;
    bool act = (sg < 8);

    ull c[4];
#pragma unroll
    for (int p = 0; p < 4; p++) c[p] = 0;

    const float* wsrc_e = g_fwT + (size_t)e * FCIN * NC + ch * FC_COLH;
    int kbeg = ksp * FC_KRANGE;

    // staging helper: fill buffer `buf` with chunk at k0
    auto stage = [&](int buf, int k0) {
        float* Wsm = fsm + buf * FC_BUF_FLOATS;
        float* Asm = Wsm + FC_WS_FLOATS;
        for (int i = tid; i < FC_KCHUNK * 25; i += 256) {
            int kk = i / 25, c2i = i % 25;
            *(float2*)&Wsm[kk * FC_COLH + c2i * 2] =
                *(const float2*)&wsrc_e[(size_t)(k0 + kk) * NC + c2i * 2];
        }
        for (int i = tid; i < FC_SPB * (FC_KCHUNK / 4); i += 256) {
            int s   = i >> 5;
            int seg = i & 31;
            float4 v = *(const float4*)&g_buf2[(size_t)sidx[s] * FCIN + k0 + seg * 4];
            *(float4*)&Asm[s * FC_AROW + seg * 4] = v;
        }
    };

    stage(0, kbeg);
    __syncthreads();

    for (int cidx = 0; cidx < FC_NCH; cidx++) {
        if (cidx + 1 < FC_NCH)
            stage((cidx + 1) & 1, kbeg + (cidx + 1) * FC_KCHUNK);
        const float* Wsm = fsm + (cidx & 1) * FC_BUF_FLOATS;
        const float* Asm = Wsm + FC_WS_FLOATS;
        if (act) {
            const float* wp = Wsm + cg * 2;
            const float* a0 = Asm + (sg * 4 + 0) * FC_AROW;
            const float* a1 = Asm + (sg * 4 + 1) * FC_AROW;
            const float* a2 = Asm + (sg * 4 + 2) * FC_AROW;
            const float* a3 = Asm + (sg * 4 + 3) * FC_AROW;
#pragma unroll 4
            for (int kk = 0; kk < FC_KCHUNK; kk++) {
                ull wab = *(const ull*)(wp + kk * FC_COLH);
                c[0] = ffma2(pk(a0[kk], a0[kk]), wab, c[0]);
                c[1] = ffma2(pk(a1[kk], a1[kk]), wab, c[1]);
                c[2] = ffma2(pk(a2[kk], a2[kk]), wab, c[2]);
                c[3] = ffma2(pk(a3[kk], a3[kk]), wab, c[3]);
            }
        }
        __syncthreads();
    }

    if (act) {
        int colb = ch * FC_COLH + cg * 2;
        float* part = g_fcp + (size_t)ksp * B * NC;
#pragma unroll
        for (int p = 0; p < 4; p++) {
            int rr = sg * 4 + p;
            if (rr < m) {
                int s = sidx[rr];
                float lo, hi;
                upk(c[p], lo, hi);
                part[(size_t)s * NC + colb]     = lo;
                part[(size_t)s * NC + colb + 1] = hi;
            }
        }
    }
}

// ---------------- FC reduce (8 partials) + aux loss (merged) ----------------
#define NRED_BLOCKS ((B * NC + 255) / 256)
__global__ void reduce_aux_kernel(const float* __restrict__ fb,
                                  const float* __restrict__ probs,
                                  float* __restrict__ out)
{
    if (blockIdx.x < NRED_BLOCKS) {
        int i = blockIdx.x * 256 + threadIdx.x;
        if (i >= B * NC) return;
        int s = i / NC;
        int c = i - s * NC;
        size_t st = (size_t)B * NC;
        float v = (((g_fcp[i]          + g_fcp[st + i])
                 +  (g_fcp[2 * st + i] + g_fcp[3 * st + i]))
                 + ((g_fcp[4 * st + i] + g_fcp[5 * st + i])
                 +  (g_fcp[6 * st + i] + g_fcp[7 * st + i])));
        out[i] = (v + fb[g_bidx[s] * NC + c]) * g_bw[s];
    } else {
        __shared__ float sm[256 * E];
        int tid = threadIdx.x;
        float s[E] = {0.f, 0.f, 0.f, 0.f};
        for (int i = tid; i < B; i += 256) {
#pragma unroll
            for (int e = 0; e < E; e++) s[e] += probs[i * E + e];
        }
#pragma unroll
        for (int e = 0; e < E; e++) sm[tid * E + e] = s[e];
        __syncthreads();
        for (int st = 128; st > 0; st >>= 1) {
            if (tid < st)
#pragma unroll
                for (int e = 0; e < E; e++) sm[tid * E + e] += sm[(tid + st) * E + e];
            __syncthreads();
        }
        if (tid == 0) {
            float a = 0.f;
#pragma unroll
            for (int e = 0; e < E; e++) {
                float m = sm[e] * (1.f / B) - 1.f / E;
                a += m * m;
            }
            out[OUT_AUX_OFF] = a * (1.f / E);
        }
    }
}

// ---------------- launch ----------------
extern "C" void kernel_launch(void* const* d_in, const int* in_sizes, int n_in,
                              void* d_out, int out_size)
{
    const float* x       = (const float*)d_in[0];
    const float* gate_cw = (const float*)d_in[1];
    const float* gate_cb = (const float*)d_in[2];
    const float* gate_fw = (const float*)d_in[3];
    const float* gate_fb = (const float*)d_in[4];
    const float* e_c1w   = (const float*)d_in[5];
    const float* e_c1b   = (const float*)d_in[6];
    const float* e_c2w   = (const float*)d_in[7];
    const float* e_c2b   = (const float*)d_in[8];
    const float* e_fw    = (const float*)d_in[9];
    const float* e_fb    = (const float*)d_in[10];
    float* out = (float*)d_out;

    cudaFuncSetAttribute(conv12_fused_kernel,
                         cudaFuncAttributeMaxDynamicSharedMemorySize, C2_SMEM);
    cudaFuncSetAttribute(fc_kernel,
                         cudaFuncAttributeMaxDynamicSharedMemorySize, FC_SMEM);

    prep_kernel<<<NW2_BLOCKS + NFW_TILES, 256>>>(e_c2w, e_fw);               // 0
    gate_router_kernel<<<B, 256>>>(x, gate_cw, gate_cb, gate_fw, gate_fb,
                                   out + OUT_PROBS_OFF);                     // 1
    conv12_fused_kernel<<<B, 512, C2_SMEM>>>(x, e_c1w, e_c1b, e_c2b);        // 2
    fc_kernel<<<E * 512, 256, FC_SMEM>>>(out);                               // 3 (ncu)
    reduce_aux_kernel<<<NRED_BLOCKS + 1, 256>>>(e_fb, out + OUT_PROBS_OFF,
                                                out);                        // 4
}